// round 12
// baseline (speedup 1.0000x reference)
#include <cuda_runtime.h>
#include <cuda_bf16.h>
#include <math.h>
#include <stdint.h>

// ---------------------------------------------------------------------------
// MultiScaleDeformableAttention, fp32 in/out.
// GEMMs: mma.sync bf16 m16n8k16. Value & output GEMMs: 3-term compensation
// (Ah*Bh + Ah*Bl + Al*Bh); QA GEMM: 1-term (error contribution ~1e-4).
// Round-12: term-major mma ordering (same-accumulator distance 2 -> 4 to
// clear HMMA accumulate-RAW stalls); query-lo conversion skipped.
// ---------------------------------------------------------------------------

#define NQ    20197
#define BSZ   2
#define EDIM  256
#define NLVL  4
#define MTOT  (BSZ * NQ)     // 40394

#define KP2   512            // [hi(256) | lo(256)] row stride
#define BK    32
#define NKIT  8              // 256 / BK
#define APAD2 72             // stage row elems (64 data + 8 pad)
#define TILE_E (128 * APAD2)
#define STAGE_B (2 * TILE_E * 2)     // 36864 B per stage (A + B)
#define SMEM_GEMM (3 * STAGE_B)      // 110592 B -> 2 CTAs/SM

#define QASTR 384            // fused SO|AW output row stride

// ------------------------------- scratch ------------------------------------
__device__ float g_V  [MTOT * EDIM];
__device__ float g_QA [(size_t)MTOT * QASTR];   // [SO(256) | AWL(128)]
__device__ __nv_bfloat16 g_Aval[(size_t)MTOT * KP2];
__device__ __nv_bfloat16 g_Aq  [(size_t)MTOT * KP2];
__device__ __nv_bfloat16 g_Atmp[(size_t)MTOT * KP2];
__device__ __nv_bfloat16 g_Bv [256 * KP2];
__device__ __nv_bfloat16 g_Bqa[QASTR * KP2];
__device__ __nv_bfloat16 g_Bo [256 * KP2];
__device__ float g_biasQA[QASTR];

// -------------------------- small PTX helpers -------------------------------
__device__ __forceinline__ uint32_t smem_u32(const void* p) {
    uint32_t a;
    asm("{ .reg .u64 t; cvta.to.shared.u64 t, %1; cvt.u32.u64 %0, t; }"
        : "=r"(a) : "l"(p));
    return a;
}
__device__ __forceinline__ void cp_async16(uint32_t dst, const void* src) {
    asm volatile("cp.async.cg.shared.global [%0], [%1], 16;"
                 :: "r"(dst), "l"(src) : "memory");
}
__device__ __forceinline__ void cp_commit() {
    asm volatile("cp.async.commit_group;" ::: "memory");
}
template <int N>
__device__ __forceinline__ void cp_wait() {
    asm volatile("cp.async.wait_group %0;" :: "n"(N) : "memory");
}
__device__ __forceinline__ void ldmatrix_x4(uint32_t* r, uint32_t addr) {
    asm volatile("ldmatrix.sync.aligned.m8n8.x4.shared.b16 {%0,%1,%2,%3}, [%4];"
                 : "=r"(r[0]), "=r"(r[1]), "=r"(r[2]), "=r"(r[3]) : "r"(addr));
}
__device__ __forceinline__ void mma_bf16(float* c, const uint32_t* a,
                                         uint32_t b0, uint32_t b1) {
    asm volatile(
        "mma.sync.aligned.m16n8k16.row.col.f32.bf16.bf16.f32 "
        "{%0,%1,%2,%3}, {%4,%5,%6,%7}, {%8,%9}, {%0,%1,%2,%3};"
        : "+f"(c[0]), "+f"(c[1]), "+f"(c[2]), "+f"(c[3])
        : "r"(a[0]), "r"(a[1]), "r"(a[2]), "r"(a[3]), "r"(b0), "r"(b1));
}

// ---------------------------------------------------------------------------
// Merged conversion kernel. Query writes hi ONLY (lo is dead: QA is 1-term).
// ---------------------------------------------------------------------------
__global__ __launch_bounds__(256) void prep_all(
    const float* __restrict__ value, const float* __restrict__ query,
    const float* __restrict__ Wv,  const float* __restrict__ Wso,
    const float* __restrict__ Waw, const float* __restrict__ Wo,
    const float* __restrict__ bso, const float* __restrict__ baw,
    int n4, int cvtB)
{
    const int bx  = blockIdx.x;
    const int tid = threadIdx.x;

    if (bx < 2 * cvtB) {
        const bool isVal = (bx < cvtB);
        const float* x = isVal ? value : query;
        __nv_bfloat16* out = isVal ? g_Aval : g_Aq;
        const int i = (bx % cvtB) * 256 + tid;
        if (i >= n4) return;
        const float4 v = ((const float4*)x)[i];
        const int row = i >> 6;
        const int c4  = (i & 63) << 2;
        __nv_bfloat16 h[4], l[4];
        const float f[4] = {v.x, v.y, v.z, v.w};
#pragma unroll
        for (int k = 0; k < 4; k++) {
            h[k] = __float2bfloat16(f[k]);
            l[k] = __float2bfloat16(f[k] - __bfloat162float(h[k]));
        }
        __nv_bfloat16* base = out + (size_t)row * KP2 + c4;
        *(uint2*)(base) = *(const uint2*)h;
        if (isVal)
            *(uint2*)(base + 256) = *(const uint2*)l;
        return;
    }

    const int idx = (bx - 2 * cvtB) * 256 + tid;
    const float* W;
    __nv_bfloat16* Bt;
    int li, N, nofs = 0;
    if (idx < 65536)        { W = Wv;  Bt = g_Bv;  li = idx;          N = 256; }
    else if (idx < 131072)  { W = Wso; Bt = g_Bqa; li = idx - 65536;  N = 256; }
    else if (idx < 163840)  { W = Waw; Bt = g_Bqa; li = idx - 131072; N = 128; nofs = 256; }
    else if (idx < 229376)  { W = Wo;  Bt = g_Bo;  li = idx - 163840; N = 256; }
    else {
        const int i = idx - 229376;
        if (i < 256)      g_biasQA[i] = bso[i];
        else if (i < 384) g_biasQA[i] = baw[i - 256];
        return;
    }
    const int k = li / N, n = li % N;
    const float v = W[li];
    const __nv_bfloat16 h = __float2bfloat16(v);
    const __nv_bfloat16 l = __float2bfloat16(v - __bfloat162float(h));
    __nv_bfloat16* base = Bt + (size_t)(n + nofs) * KP2 + k;
    base[0]   = h;
    base[256] = l;
}

// ---------------------------------------------------------------------------
// GEMM core: BM=128, BN=128, BK=32, 8 warps (4x2), warp 32x64, 3-stage
// cp.async. nterms=3: full compensation; nterms=1: Ah*Bh only.
// mma issue order is TERM-major with (mi, n-half) inner -> same-accumulator
// ops are 4 instructions apart (clears HMMA accumulate-RAW stalls).
// ---------------------------------------------------------------------------
__device__ __forceinline__ void gemm_body(
    const __nv_bfloat16* __restrict__ A, const __nv_bfloat16* __restrict__ Bt,
    const float* __restrict__ bias, const float* __restrict__ res,
    float* __restrict__ C, int M, int N, int m0, int n0, char* smem,
    int nterms)
{
    const uint32_t sBase = smem_u32(smem);
    const int tid  = threadIdx.x;
    const int lane = tid & 31;
    const int wid  = tid >> 5;
    const int wm   = wid & 3;
    const int wn   = wid >> 2;

    auto load_stage = [&](int stg, int kt) {
        const int kbase = kt * BK;
        const uint32_t sA = sBase + (uint32_t)stg * STAGE_B;
        const uint32_t sB = sA + TILE_E * 2;
#pragma unroll
        for (int it = 0; it < 4; it++) {
            const int c   = tid + it * 256;
            const int row = c >> 3;
            const int seg = (c & 7) << 3;
            if (nterms == 1 && seg >= 32) continue;   // skip lo halves
            const int gcol = (seg < 32) ? (kbase + seg) : (256 + kbase + seg - 32);
            const uint32_t soff = (uint32_t)(row * APAD2 + seg) * 2;
            const int ar = min(m0 + row, M - 1);
            cp_async16(sA + soff, A + (size_t)ar * KP2 + gcol);
            cp_async16(sB + soff, Bt + (size_t)(n0 + row) * KP2 + gcol);
        }
    };

    float acc[2][8][4];
#pragma unroll
    for (int mi = 0; mi < 2; mi++)
#pragma unroll
        for (int nj = 0; nj < 8; nj++)
#pragma unroll
            for (int k = 0; k < 4; k++) acc[mi][nj][k] = 0.f;

    load_stage(0, 0); cp_commit();
    load_stage(1, 1); cp_commit();

    int stg = 0;
#pragma unroll 1
    for (int kt = 0; kt < NKIT; kt++) {
        cp_wait<1>();
        __syncthreads();

        if (kt + 2 < NKIT) load_stage((stg + 2) % 3, kt + 2);
        cp_commit();   // empty groups at tail keep wait<1> exact

        const uint32_t aB = sBase + (uint32_t)stg * STAGE_B;
        const uint32_t bB = aB + TILE_E * 2;

#pragma unroll
        for (int ks = 0; ks < 2; ks++) {
            uint32_t ah[2][4], al[2][4];
#pragma unroll
            for (int mi = 0; mi < 2; mi++) {
                const int row = wm * 32 + mi * 16 + (lane & 15);
                const int col = ks * 16 + ((lane >> 4) << 3);
                ldmatrix_x4(ah[mi], aB + (uint32_t)(row * APAD2 + col) * 2);
                if (nterms == 3)
                    ldmatrix_x4(al[mi], aB + (uint32_t)(row * APAD2 + 32 + col) * 2);
            }
#pragma unroll
            for (int njp = 0; njp < 4; njp++) {
                const int row = wn * 64 + njp * 16 + ((lane >> 4) & 1) * 8 + (lane & 7);
                const int col = ks * 16 + ((lane >> 3) & 1) * 8;
                uint32_t bh[4], bl[4];
                ldmatrix_x4(bh, bB + (uint32_t)(row * APAD2 + col) * 2);
                if (nterms == 3)
                    ldmatrix_x4(bl, bB + (uint32_t)(row * APAD2 + 32 + col) * 2);

                float* a00 = acc[0][njp * 2];
                float* a01 = acc[0][njp * 2 + 1];
                float* a10 = acc[1][njp * 2];
                float* a11 = acc[1][njp * 2 + 1];

                // term hh (distance-4 same-acc spacing)
                mma_bf16(a00, ah[0], bh[0], bh[1]);
                mma_bf16(a01, ah[0], bh[2], bh[3]);
                mma_bf16(a10, ah[1], bh[0], bh[1]);
                mma_bf16(a11, ah[1], bh[2], bh[3]);
                if (nterms == 3) {
                    // term hl
                    mma_bf16(a00, ah[0], bl[0], bl[1]);
                    mma_bf16(a01, ah[0], bl[2], bl[3]);
                    mma_bf16(a10, ah[1], bl[0], bl[1]);
                    mma_bf16(a11, ah[1], bl[2], bl[3]);
                    // term lh
                    mma_bf16(a00, al[0], bh[0], bh[1]);
                    mma_bf16(a01, al[0], bh[2], bh[3]);
                    mma_bf16(a10, al[1], bh[0], bh[1]);
                    mma_bf16(a11, al[1], bh[2], bh[3]);
                }
            }
        }
        stg = (stg + 1) % 3;
    }

#pragma unroll
    for (int mi = 0; mi < 2; mi++) {
#pragma unroll
        for (int nj = 0; nj < 8; nj++) {
            const int col = n0 + wn * 64 + nj * 8 + (lane & 3) * 2;
            const int r0  = m0 + wm * 32 + mi * 16 + (lane >> 2);
            const int r1  = r0 + 8;
            const float b0 = bias[col], b1 = bias[col + 1];
            if (r0 < M) {
                float2 o = make_float2(acc[mi][nj][0] + b0, acc[mi][nj][1] + b1);
                if (res) {
                    const float2 rv = *(const float2*)(res + (size_t)r0 * N + col);
                    o.x += rv.x; o.y += rv.y;
                }
                *(float2*)(C + (size_t)r0 * N + col) = o;
            }
            if (r1 < M) {
                float2 o = make_float2(acc[mi][nj][2] + b0, acc[mi][nj][3] + b1);
                if (res) {
                    const float2 rv = *(const float2*)(res + (size_t)r1 * N + col);
                    o.x += rv.x; o.y += rv.y;
                }
                *(float2*)(C + (size_t)r1 * N + col) = o;
            }
        }
    }
}

// Fused value+QA GEMM: y 0-1 -> value (3-term), y 2-4 -> QA (1-term).
__global__ __launch_bounds__(256, 2) void gemm_vqa(
    const __nv_bfloat16* __restrict__ Av, const __nv_bfloat16* __restrict__ Bv,
    const float* __restrict__ bv, float* __restrict__ Cv,
    const __nv_bfloat16* __restrict__ Aq, const __nv_bfloat16* __restrict__ Bqa,
    const float* __restrict__ bqa, float* __restrict__ Cqa, int M)
{
    extern __shared__ __align__(16) char smem[];
    const int y = blockIdx.y;
    const int m0 = blockIdx.x * 128;
    if (y < 2)
        gemm_body(Av, Bv, bv, nullptr, Cv, M, 256, m0, y * 128, smem, 3);
    else
        gemm_body(Aq, Bqa, bqa, nullptr, Cqa, M, QASTR, m0, (y - 2) * 128, smem, 1);
}

// Output GEMM (3-term, bias + residual epilogue).
__global__ __launch_bounds__(256, 2) void gemm_out(
    const __nv_bfloat16* __restrict__ A, const __nv_bfloat16* __restrict__ Bt,
    const float* __restrict__ bias, const float* __restrict__ res,
    float* __restrict__ C, int M)
{
    extern __shared__ __align__(16) char smem[];
    gemm_body(A, Bt, bias, res, C, M, 256, blockIdx.x * 128, blockIdx.y * 128,
              smem, 3);
}

// ---------------------------------------------------------------------------
// Sampler (round-6 float4 version — best measured). Block = 4 queries.
// ---------------------------------------------------------------------------
__global__ __launch_bounds__(256) void msda_sample4(
    const float* __restrict__ V, const float* __restrict__ QA,
    const float* __restrict__ refp,
    const int* __restrict__ shapes, const int* __restrict__ starts,
    __nv_bfloat16* __restrict__ outCat, int M)
{
    __shared__ int4   sOff[4][16][8];
    __shared__ float4 sW  [4][16][8];

    const int tid = threadIdx.x;

    // Phase A
    {
        const int wi  = tid << 1;
        const int bqL = wi >> 7;
        const int h   = (wi >> 4) & 7;
        const int pt0 = wi & 15;
        int bq = blockIdx.x * 4 + bqL;
        bq = min(bq, M - 1);

        const float2 lg = *(const float2*)(QA + (size_t)bq * QASTR + 256 + h * 16 + pt0);
        float mx = fmaxf(lg.x, lg.y);
#pragma unroll
        for (int off = 4; off; off >>= 1)
            mx = fmaxf(mx, __shfl_xor_sync(0xffffffffu, mx, off));
        const float e0 = expf(lg.x - mx);
        const float e1 = expf(lg.y - mx);
        float sm = e0 + e1;
#pragma unroll
        for (int off = 4; off; off >>= 1)
            sm += __shfl_xor_sync(0xffffffffu, sm, off);
        const float inv = 1.f / sm;

        const int l = pt0 >> 2;
        const int H = shapes[2 * l + 0];
        const int W = shapes[2 * l + 1];
        const int st = starts[l];
        const float2 rp = *(const float2*)(refp + ((size_t)bq * NLVL + l) * 2);
        const float4 so = *(const float4*)(QA + (size_t)bq * QASTR + h * 32 + pt0 * 2);

#pragma unroll
        for (int k = 0; k < 2; k++) {
            const int pt = pt0 + k;
            const float aw  = (k ? e1 : e0) * inv;
            const float sox = k ? so.z : so.x;
            const float soy = k ? so.w : so.y;

            const float x = fmaf(rp.x, (float)W, sox) - 0.5f;
            const float y = fmaf(rp.y, (float)H, soy) - 0.5f;
            const float xf = floorf(x), yf = floorf(y);
            const int x0 = (int)xf, y0 = (int)yf;
            const float wx1 = x - xf, wx0 = 1.f - wx1;
            const float wy1 = y - yf, wy0 = 1.f - wy1;

            const bool vx0 = (x0 >= 0) && (x0 < W);
            const bool vx1 = (x0 + 1 >= 0) && (x0 + 1 < W);
            const bool vy0 = (y0 >= 0) && (y0 < H);
            const bool vy1 = (y0 + 1 >= 0) && (y0 + 1 < H);

            const int cx0 = max(0, min(x0,     W - 1));
            const int cx1 = max(0, min(x0 + 1, W - 1));
            const int cy0 = max(0, min(y0,     H - 1));
            const int cy1 = max(0, min(y0 + 1, H - 1));

            int4 o;
            o.x = st + cy0 * W + cx0;
            o.y = st + cy0 * W + cx1;
            o.z = st + cy1 * W + cx0;
            o.w = st + cy1 * W + cx1;

            float4 w4;
            w4.x = (vx0 && vy0) ? wx0 * wy0 * aw : 0.f;
            w4.y = (vx1 && vy0) ? wx1 * wy0 * aw : 0.f;
            w4.z = (vx0 && vy1) ? wx0 * wy1 * aw : 0.f;
            w4.w = (vx1 && vy1) ? wx1 * wy1 * aw : 0.f;

            sOff[bqL][pt][h] = o;
            sW  [bqL][pt][h] = w4;
        }
    }
    __syncthreads();

    // Phase B
    const int warpId = tid >> 5;
    const int lane   = tid & 31;
    const int bqL    = warpId >> 1;
    const int h      = ((warpId & 1) << 2) + (lane >> 3);
    const int c4     = lane & 7;
    const int bq     = blockIdx.x * 4 + bqL;
    if (bq >= M) return;
    const int b = bq / NQ;

    const float* vb = V + (size_t)b * NQ * EDIM + h * 32 + c4 * 4;

    float4 acc = make_float4(0.f, 0.f, 0.f, 0.f);
#pragma unroll
    for (int pt = 0; pt < 16; pt++) {
        const int4   o = sOff[bqL][pt][h];
        const float4 w = sW  [bqL][pt][h];

        const float4 v0 = *(const float4*)(vb + (size_t)o.x * EDIM);
        const float4 v1 = *(const float4*)(vb + (size_t)o.y * EDIM);
        const float4 v2 = *(const float4*)(vb + (size_t)o.z * EDIM);
        const float4 v3 = *(const float4*)(vb + (size_t)o.w * EDIM);

        acc.x = fmaf(w.x, v0.x, acc.x); acc.y = fmaf(w.x, v0.y, acc.y);
        acc.z = fmaf(w.x, v0.z, acc.z); acc.w = fmaf(w.x, v0.w, acc.w);
        acc.x = fmaf(w.y, v1.x, acc.x); acc.y = fmaf(w.y, v1.y, acc.y);
        acc.z = fmaf(w.y, v1.z, acc.z); acc.w = fmaf(w.y, v1.w, acc.w);
        acc.x = fmaf(w.z, v2.x, acc.x); acc.y = fmaf(w.z, v2.y, acc.y);
        acc.z = fmaf(w.z, v2.z, acc.z); acc.w = fmaf(w.z, v2.w, acc.w);
        acc.x = fmaf(w.w, v3.x, acc.x); acc.y = fmaf(w.w, v3.y, acc.y);
        acc.z = fmaf(w.w, v3.z, acc.z); acc.w = fmaf(w.w, v3.w, acc.w);
    }

    __nv_bfloat16 hh[4], ll[4];
    const float f[4] = {acc.x, acc.y, acc.z, acc.w};
#pragma unroll
    for (int k = 0; k < 4; k++) {
        hh[k] = __float2bfloat16(f[k]);
        ll[k] = __float2bfloat16(f[k] - __bfloat162float(hh[k]));
    }
    __nv_bfloat16* base = outCat + (size_t)bq * KP2 + h * 32 + c4 * 4;
    *(uint2*)(base)       = *(const uint2*)hh;
    *(uint2*)(base + 256) = *(const uint2*)ll;
}

// ---------------------------------------------------------------------------
// Launch
// ---------------------------------------------------------------------------
extern "C" void kernel_launch(void* const* d_in, const int* in_sizes, int n_in,
                              void* d_out, int out_size)
{
    const float* query  = (const float*)d_in[0];
    const float* value  = (const float*)d_in[1];
    const float* refp   = (const float*)d_in[2];
    const int*   shapes = (const int*)  d_in[3];
    const int*   starts = (const int*)  d_in[4];
    const float* Wv  = (const float*)d_in[5];
    const float* bv  = (const float*)d_in[6];
    const float* Wso = (const float*)d_in[7];
    const float* bso = (const float*)d_in[8];
    const float* Waw = (const float*)d_in[9];
    const float* baw = (const float*)d_in[10];
    const float* Wo  = (const float*)d_in[11];
    const float* bo  = (const float*)d_in[12];
    float* out = (float*)d_out;

    const int M = in_sizes[0] / EDIM;   // 40394

    float *pV, *pQA, *pBiasQA;
    __nv_bfloat16 *pAval, *pAq, *pAtmp, *pBv, *pBqa, *pBo;
    cudaGetSymbolAddress((void**)&pV,     g_V);
    cudaGetSymbolAddress((void**)&pQA,    g_QA);
    cudaGetSymbolAddress((void**)&pBiasQA,g_biasQA);
    cudaGetSymbolAddress((void**)&pAval,  g_Aval);
    cudaGetSymbolAddress((void**)&pAq,    g_Aq);
    cudaGetSymbolAddress((void**)&pAtmp,  g_Atmp);
    cudaGetSymbolAddress((void**)&pBv,    g_Bv);
    cudaGetSymbolAddress((void**)&pBqa,   g_Bqa);
    cudaGetSymbolAddress((void**)&pBo,    g_Bo);

    cudaFuncSetAttribute(gemm_vqa, cudaFuncAttributeMaxDynamicSharedMemorySize, SMEM_GEMM);
    cudaFuncSetAttribute(gemm_out, cudaFuncAttributeMaxDynamicSharedMemorySize, SMEM_GEMM);

    const int n4 = M * (EDIM / 4);
    const int cvtB = (n4 + 255) / 256;
    const int wB   = (229760 + 255) / 256;
    const int mTiles = (M + 127) / 128;

    prep_all<<<2 * cvtB + wB, 256>>>(value, query, Wv, Wso, Waw, Wo, bso, baw,
                                     n4, cvtB);
    gemm_vqa<<<dim3(mTiles, 5), 256, SMEM_GEMM>>>(
        pAval, pBv, bv, pV, pAq, pBqa, pBiasQA, pQA, M);
    msda_sample4<<<(M + 3) / 4, 256>>>(pV, pQA, refp, shapes, starts, pAtmp, M);
    gemm_out<<<dim3(mTiles, 2), 256, SMEM_GEMM>>>(pAtmp, pBo, bo, query, out, M);
}

// round 14
// speedup vs baseline: 1.1595x; 1.1595x over previous
#include <cuda_runtime.h>
#include <cuda_bf16.h>
#include <cuda_fp16.h>
#include <math.h>
#include <stdint.h>

// ---------------------------------------------------------------------------
// MultiScaleDeformableAttention, fp32 in/out.
// GEMMs: mma.sync bf16 m16n8k16. Value & output GEMMs: 3-term compensation;
// QA GEMM: 1-term. Round-14 = Round-13 + fix (QA output pointer was dropped):
//   (a) gemm_out: 592-CTA stride loop over 632 tiles (no wave quantization)
//   (b) projected V stored fp16 (halves sampler gather bytes)
// ---------------------------------------------------------------------------

#define NQ    20197
#define BSZ   2
#define EDIM  256
#define NLVL  4
#define MTOT  (BSZ * NQ)     // 40394

#define KP2   512            // [hi(256) | lo(256)] row stride
#define BK    32
#define NKIT  8              // 256 / BK
#define APAD2 72             // stage row elems (64 data + 8 pad)
#define TILE_E (128 * APAD2)
#define STAGE_B (2 * TILE_E * 2)     // 36864 B per stage (A + B)
#define SMEM_GEMM (3 * STAGE_B)      // 110592 B -> 2 CTAs/SM

#define QASTR 384            // fused SO|AW output row stride

// ------------------------------- scratch ------------------------------------
__device__ __half g_Vh [MTOT * EDIM];           // projected value, fp16
__device__ float  g_QA [(size_t)MTOT * QASTR];  // [SO(256) | AWL(128)]
__device__ __nv_bfloat16 g_Aval[(size_t)MTOT * KP2];
__device__ __nv_bfloat16 g_Aq  [(size_t)MTOT * KP2];
__device__ __nv_bfloat16 g_Atmp[(size_t)MTOT * KP2];
__device__ __nv_bfloat16 g_Bv [256 * KP2];
__device__ __nv_bfloat16 g_Bqa[QASTR * KP2];
__device__ __nv_bfloat16 g_Bo [256 * KP2];
__device__ float g_biasQA[QASTR];

// -------------------------- small PTX helpers -------------------------------
__device__ __forceinline__ uint32_t smem_u32(const void* p) {
    uint32_t a;
    asm("{ .reg .u64 t; cvta.to.shared.u64 t, %1; cvt.u32.u64 %0, t; }"
        : "=r"(a) : "l"(p));
    return a;
}
__device__ __forceinline__ void cp_async16(uint32_t dst, const void* src) {
    asm volatile("cp.async.cg.shared.global [%0], [%1], 16;"
                 :: "r"(dst), "l"(src) : "memory");
}
__device__ __forceinline__ void cp_commit() {
    asm volatile("cp.async.commit_group;" ::: "memory");
}
template <int N>
__device__ __forceinline__ void cp_wait() {
    asm volatile("cp.async.wait_group %0;" :: "n"(N) : "memory");
}
__device__ __forceinline__ void ldmatrix_x4(uint32_t* r, uint32_t addr) {
    asm volatile("ldmatrix.sync.aligned.m8n8.x4.shared.b16 {%0,%1,%2,%3}, [%4];"
                 : "=r"(r[0]), "=r"(r[1]), "=r"(r[2]), "=r"(r[3]) : "r"(addr));
}
__device__ __forceinline__ void mma_bf16(float* c, const uint32_t* a,
                                         uint32_t b0, uint32_t b1) {
    asm volatile(
        "mma.sync.aligned.m16n8k16.row.col.f32.bf16.bf16.f32 "
        "{%0,%1,%2,%3}, {%4,%5,%6,%7}, {%8,%9}, {%0,%1,%2,%3};"
        : "+f"(c[0]), "+f"(c[1]), "+f"(c[2]), "+f"(c[3])
        : "r"(a[0]), "r"(a[1]), "r"(a[2]), "r"(a[3]), "r"(b0), "r"(b1));
}

// ---------------------------------------------------------------------------
// Merged conversion kernel. Query writes hi ONLY (QA GEMM is 1-term).
// ---------------------------------------------------------------------------
__global__ __launch_bounds__(256) void prep_all(
    const float* __restrict__ value, const float* __restrict__ query,
    const float* __restrict__ Wv,  const float* __restrict__ Wso,
    const float* __restrict__ Waw, const float* __restrict__ Wo,
    const float* __restrict__ bso, const float* __restrict__ baw,
    int n4, int cvtB)
{
    const int bx  = blockIdx.x;
    const int tid = threadIdx.x;

    if (bx < 2 * cvtB) {
        const bool isVal = (bx < cvtB);
        const float* x = isVal ? value : query;
        __nv_bfloat16* out = isVal ? g_Aval : g_Aq;
        const int i = (bx % cvtB) * 256 + tid;
        if (i >= n4) return;
        const float4 v = ((const float4*)x)[i];
        const int row = i >> 6;
        const int c4  = (i & 63) << 2;
        __nv_bfloat16 h[4], l[4];
        const float f[4] = {v.x, v.y, v.z, v.w};
#pragma unroll
        for (int k = 0; k < 4; k++) {
            h[k] = __float2bfloat16(f[k]);
            l[k] = __float2bfloat16(f[k] - __bfloat162float(h[k]));
        }
        __nv_bfloat16* base = out + (size_t)row * KP2 + c4;
        *(uint2*)(base) = *(const uint2*)h;
        if (isVal)
            *(uint2*)(base + 256) = *(const uint2*)l;
        return;
    }

    const int idx = (bx - 2 * cvtB) * 256 + tid;
    const float* W;
    __nv_bfloat16* Bt;
    int li, N, nofs = 0;
    if (idx < 65536)        { W = Wv;  Bt = g_Bv;  li = idx;          N = 256; }
    else if (idx < 131072)  { W = Wso; Bt = g_Bqa; li = idx - 65536;  N = 256; }
    else if (idx < 163840)  { W = Waw; Bt = g_Bqa; li = idx - 131072; N = 128; nofs = 256; }
    else if (idx < 229376)  { W = Wo;  Bt = g_Bo;  li = idx - 163840; N = 256; }
    else {
        const int i = idx - 229376;
        if (i < 256)      g_biasQA[i] = bso[i];
        else if (i < 384) g_biasQA[i] = baw[i - 256];
        return;
    }
    const int k = li / N, n = li % N;
    const float v = W[li];
    const __nv_bfloat16 h = __float2bfloat16(v);
    const __nv_bfloat16 l = __float2bfloat16(v - __bfloat162float(h));
    __nv_bfloat16* base = Bt + (size_t)(n + nofs) * KP2 + k;
    base[0]   = h;
    base[256] = l;
}

// ---------------------------------------------------------------------------
// GEMM core: BM=128, BN=128, BK=32, 8 warps (4x2), warp 32x64, 3-stage
// cp.async. nterms=3: full compensation; nterms=1: Ah*Bh only.
// If Ch != nullptr, epilogue writes fp16 to Ch (N must be 256, no residual).
// ---------------------------------------------------------------------------
__device__ __forceinline__ void gemm_body(
    const __nv_bfloat16* __restrict__ A, const __nv_bfloat16* __restrict__ Bt,
    const float* __restrict__ bias, const float* __restrict__ res,
    float* __restrict__ C, __half* __restrict__ Ch,
    int M, int N, int m0, int n0, char* smem, int nterms)
{
    const uint32_t sBase = smem_u32(smem);
    const int tid  = threadIdx.x;
    const int lane = tid & 31;
    const int wid  = tid >> 5;
    const int wm   = wid & 3;
    const int wn   = wid >> 2;

    auto load_stage = [&](int stg, int kt) {
        const int kbase = kt * BK;
        const uint32_t sA = sBase + (uint32_t)stg * STAGE_B;
        const uint32_t sB = sA + TILE_E * 2;
#pragma unroll
        for (int it = 0; it < 4; it++) {
            const int c   = tid + it * 256;
            const int row = c >> 3;
            const int seg = (c & 7) << 3;
            if (nterms == 1 && seg >= 32) continue;   // skip lo halves
            const int gcol = (seg < 32) ? (kbase + seg) : (256 + kbase + seg - 32);
            const uint32_t soff = (uint32_t)(row * APAD2 + seg) * 2;
            const int ar = min(m0 + row, M - 1);
            cp_async16(sA + soff, A + (size_t)ar * KP2 + gcol);
            cp_async16(sB + soff, Bt + (size_t)(n0 + row) * KP2 + gcol);
        }
    };

    float acc[2][8][4];
#pragma unroll
    for (int mi = 0; mi < 2; mi++)
#pragma unroll
        for (int nj = 0; nj < 8; nj++)
#pragma unroll
            for (int k = 0; k < 4; k++) acc[mi][nj][k] = 0.f;

    load_stage(0, 0); cp_commit();
    load_stage(1, 1); cp_commit();

    int stg = 0;
#pragma unroll 1
    for (int kt = 0; kt < NKIT; kt++) {
        cp_wait<1>();
        __syncthreads();

        if (kt + 2 < NKIT) load_stage((stg + 2) % 3, kt + 2);
        cp_commit();   // empty groups at tail keep wait<1> exact

        const uint32_t aB = sBase + (uint32_t)stg * STAGE_B;
        const uint32_t bB = aB + TILE_E * 2;

#pragma unroll
        for (int ks = 0; ks < 2; ks++) {
            uint32_t ah[2][4], al[2][4];
#pragma unroll
            for (int mi = 0; mi < 2; mi++) {
                const int row = wm * 32 + mi * 16 + (lane & 15);
                const int col = ks * 16 + ((lane >> 4) << 3);
                ldmatrix_x4(ah[mi], aB + (uint32_t)(row * APAD2 + col) * 2);
                if (nterms == 3)
                    ldmatrix_x4(al[mi], aB + (uint32_t)(row * APAD2 + 32 + col) * 2);
            }
#pragma unroll
            for (int njp = 0; njp < 4; njp++) {
                const int row = wn * 64 + njp * 16 + ((lane >> 4) & 1) * 8 + (lane & 7);
                const int col = ks * 16 + ((lane >> 3) & 1) * 8;
                uint32_t bh[4], bl[4];
                ldmatrix_x4(bh, bB + (uint32_t)(row * APAD2 + col) * 2);
                if (nterms == 3)
                    ldmatrix_x4(bl, bB + (uint32_t)(row * APAD2 + 32 + col) * 2);

                float* a00 = acc[0][njp * 2];
                float* a01 = acc[0][njp * 2 + 1];
                float* a10 = acc[1][njp * 2];
                float* a11 = acc[1][njp * 2 + 1];

                mma_bf16(a00, ah[0], bh[0], bh[1]);
                mma_bf16(a01, ah[0], bh[2], bh[3]);
                mma_bf16(a10, ah[1], bh[0], bh[1]);
                mma_bf16(a11, ah[1], bh[2], bh[3]);
                if (nterms == 3) {
                    mma_bf16(a00, ah[0], bl[0], bl[1]);
                    mma_bf16(a01, ah[0], bl[2], bl[3]);
                    mma_bf16(a10, ah[1], bl[0], bl[1]);
                    mma_bf16(a11, ah[1], bl[2], bl[3]);
                    mma_bf16(a00, al[0], bh[0], bh[1]);
                    mma_bf16(a01, al[0], bh[2], bh[3]);
                    mma_bf16(a10, al[1], bh[0], bh[1]);
                    mma_bf16(a11, al[1], bh[2], bh[3]);
                }
            }
        }
        stg = (stg + 1) % 3;
    }

#pragma unroll
    for (int mi = 0; mi < 2; mi++) {
#pragma unroll
        for (int nj = 0; nj < 8; nj++) {
            const int col = n0 + wn * 64 + nj * 8 + (lane & 3) * 2;
            const int r0  = m0 + wm * 32 + mi * 16 + (lane >> 2);
            const int r1  = r0 + 8;
            const float b0 = bias[col], b1 = bias[col + 1];
            if (Ch) {
                if (r0 < M)
                    *(__half2*)(Ch + (size_t)r0 * 256 + col) =
                        __floats2half2_rn(acc[mi][nj][0] + b0, acc[mi][nj][1] + b1);
                if (r1 < M)
                    *(__half2*)(Ch + (size_t)r1 * 256 + col) =
                        __floats2half2_rn(acc[mi][nj][2] + b0, acc[mi][nj][3] + b1);
            } else {
                if (r0 < M) {
                    float2 o = make_float2(acc[mi][nj][0] + b0, acc[mi][nj][1] + b1);
                    if (res) {
                        const float2 rv = *(const float2*)(res + (size_t)r0 * N + col);
                        o.x += rv.x; o.y += rv.y;
                    }
                    *(float2*)(C + (size_t)r0 * N + col) = o;
                }
                if (r1 < M) {
                    float2 o = make_float2(acc[mi][nj][2] + b0, acc[mi][nj][3] + b1);
                    if (res) {
                        const float2 rv = *(const float2*)(res + (size_t)r1 * N + col);
                        o.x += rv.x; o.y += rv.y;
                    }
                    *(float2*)(C + (size_t)r1 * N + col) = o;
                }
            }
        }
    }
}

// Fused value+QA GEMM: y 0-1 -> value (3-term, fp16 out), y 2-4 -> QA (1-term).
__global__ __launch_bounds__(256, 2) void gemm_vqa(
    const __nv_bfloat16* __restrict__ Av, const __nv_bfloat16* __restrict__ Bv,
    const float* __restrict__ bv, __half* __restrict__ Vh,
    const __nv_bfloat16* __restrict__ Aq, const __nv_bfloat16* __restrict__ Bqa,
    const float* __restrict__ bqa, float* __restrict__ Cqa, int M)
{
    extern __shared__ __align__(16) char smem[];
    const int y = blockIdx.y;
    const int m0 = blockIdx.x * 128;
    if (y < 2)
        gemm_body(Av, Bv, bv, nullptr, nullptr, Vh, M, 256, m0, y * 128, smem, 3);
    else
        gemm_body(Aq, Bqa, bqa, nullptr, Cqa, nullptr, M, QASTR, m0,
                  (y - 2) * 128, smem, 1);   // FIX: Cqa was nullptr in R13
}

// Output GEMM: stride-loop over nT tiles (grid = min(nT, 592)) to avoid
// wave quantization. Tile t -> m = t>>1, n = t&1 (pairs share A rows in L2).
__global__ __launch_bounds__(256, 2) void gemm_out(
    const __nv_bfloat16* __restrict__ A, const __nv_bfloat16* __restrict__ Bt,
    const float* __restrict__ bias, const float* __restrict__ res,
    float* __restrict__ C, int M, int nT)
{
    extern __shared__ __align__(16) char smem[];
    for (int t = blockIdx.x; t < nT; t += gridDim.x) {
        if (t != (int)blockIdx.x) __syncthreads();   // stage-buffer reuse guard
        gemm_body(A, Bt, bias, res, C, nullptr, M, 256,
                  (t >> 1) * 128, (t & 1) * 128, smem, 3);
    }
}

// ---------------------------------------------------------------------------
// Sampler (R6 layout, fp16 V). Block = 4 queries; Phase B: 8 lanes x uint2
// (8B) per head -> 64B per corner gather.
// ---------------------------------------------------------------------------
__global__ __launch_bounds__(256) void msda_sample4(
    const __half* __restrict__ V, const float* __restrict__ QA,
    const float* __restrict__ refp,
    const int* __restrict__ shapes, const int* __restrict__ starts,
    __nv_bfloat16* __restrict__ outCat, int M)
{
    __shared__ int4   sOff[4][16][8];
    __shared__ float4 sW  [4][16][8];

    const int tid = threadIdx.x;

    // Phase A
    {
        const int wi  = tid << 1;
        const int bqL = wi >> 7;
        const int h   = (wi >> 4) & 7;
        const int pt0 = wi & 15;
        int bq = blockIdx.x * 4 + bqL;
        bq = min(bq, M - 1);

        const float2 lg = *(const float2*)(QA + (size_t)bq * QASTR + 256 + h * 16 + pt0);
        float mx = fmaxf(lg.x, lg.y);
#pragma unroll
        for (int off = 4; off; off >>= 1)
            mx = fmaxf(mx, __shfl_xor_sync(0xffffffffu, mx, off));
        const float e0 = expf(lg.x - mx);
        const float e1 = expf(lg.y - mx);
        float sm = e0 + e1;
#pragma unroll
        for (int off = 4; off; off >>= 1)
            sm += __shfl_xor_sync(0xffffffffu, sm, off);
        const float inv = 1.f / sm;

        const int l = pt0 >> 2;
        const int H = shapes[2 * l + 0];
        const int W = shapes[2 * l + 1];
        const int st = starts[l];
        const float2 rp = *(const float2*)(refp + ((size_t)bq * NLVL + l) * 2);
        const float4 so = *(const float4*)(QA + (size_t)bq * QASTR + h * 32 + pt0 * 2);

#pragma unroll
        for (int k = 0; k < 2; k++) {
            const int pt = pt0 + k;
            const float aw  = (k ? e1 : e0) * inv;
            const float sox = k ? so.z : so.x;
            const float soy = k ? so.w : so.y;

            const float x = fmaf(rp.x, (float)W, sox) - 0.5f;
            const float y = fmaf(rp.y, (float)H, soy) - 0.5f;
            const float xf = floorf(x), yf = floorf(y);
            const int x0 = (int)xf, y0 = (int)yf;
            const float wx1 = x - xf, wx0 = 1.f - wx1;
            const float wy1 = y - yf, wy0 = 1.f - wy1;

            const bool vx0 = (x0 >= 0) && (x0 < W);
            const bool vx1 = (x0 + 1 >= 0) && (x0 + 1 < W);
            const bool vy0 = (y0 >= 0) && (y0 < H);
            const bool vy1 = (y0 + 1 >= 0) && (y0 + 1 < H);

            const int cx0 = max(0, min(x0,     W - 1));
            const int cx1 = max(0, min(x0 + 1, W - 1));
            const int cy0 = max(0, min(y0,     H - 1));
            const int cy1 = max(0, min(y0 + 1, H - 1));

            int4 o;
            o.x = st + cy0 * W + cx0;
            o.y = st + cy0 * W + cx1;
            o.z = st + cy1 * W + cx0;
            o.w = st + cy1 * W + cx1;

            float4 w4;
            w4.x = (vx0 && vy0) ? wx0 * wy0 * aw : 0.f;
            w4.y = (vx1 && vy0) ? wx1 * wy0 * aw : 0.f;
            w4.z = (vx0 && vy1) ? wx0 * wy1 * aw : 0.f;
            w4.w = (vx1 && vy1) ? wx1 * wy1 * aw : 0.f;

            sOff[bqL][pt][h] = o;
            sW  [bqL][pt][h] = w4;
        }
    }
    __syncthreads();

    // Phase B: warp = (q, head-pair); 8 lanes x uint2 per head.
    const int warpId = tid >> 5;
    const int lane   = tid & 31;
    const int bqL    = warpId >> 1;
    const int h      = ((warpId & 1) << 2) + (lane >> 3);
    const int c4     = lane & 7;
    const int bq     = blockIdx.x * 4 + bqL;
    if (bq >= M) return;
    const int b = bq / NQ;

    const __half* vb = V + (size_t)b * NQ * EDIM + h * 32 + c4 * 4;

    float4 acc = make_float4(0.f, 0.f, 0.f, 0.f);
#pragma unroll
    for (int pt = 0; pt < 16; pt++) {
        const int4   o = sOff[bqL][pt][h];
        const float4 w = sW  [bqL][pt][h];

        const uint2 u0 = *(const uint2*)(vb + (size_t)o.x * EDIM);
        const uint2 u1 = *(const uint2*)(vb + (size_t)o.y * EDIM);
        const uint2 u2 = *(const uint2*)(vb + (size_t)o.z * EDIM);
        const uint2 u3 = *(const uint2*)(vb + (size_t)o.w * EDIM);

        const float2 p00 = __half22float2(*(const __half2*)&u0.x);
        const float2 p01 = __half22float2(*(const __half2*)&u0.y);
        const float2 p10 = __half22float2(*(const __half2*)&u1.x);
        const float2 p11 = __half22float2(*(const __half2*)&u1.y);
        const float2 p20 = __half22float2(*(const __half2*)&u2.x);
        const float2 p21 = __half22float2(*(const __half2*)&u2.y);
        const float2 p30 = __half22float2(*(const __half2*)&u3.x);
        const float2 p31 = __half22float2(*(const __half2*)&u3.y);

        acc.x = fmaf(w.x, p00.x, acc.x); acc.y = fmaf(w.x, p00.y, acc.y);
        acc.z = fmaf(w.x, p01.x, acc.z); acc.w = fmaf(w.x, p01.y, acc.w);
        acc.x = fmaf(w.y, p10.x, acc.x); acc.y = fmaf(w.y, p10.y, acc.y);
        acc.z = fmaf(w.y, p11.x, acc.z); acc.w = fmaf(w.y, p11.y, acc.w);
        acc.x = fmaf(w.z, p20.x, acc.x); acc.y = fmaf(w.z, p20.y, acc.y);
        acc.z = fmaf(w.z, p21.x, acc.z); acc.w = fmaf(w.z, p21.y, acc.w);
        acc.x = fmaf(w.w, p30.x, acc.x); acc.y = fmaf(w.w, p30.y, acc.y);
        acc.z = fmaf(w.w, p31.x, acc.z); acc.w = fmaf(w.w, p31.y, acc.w);
    }

    __nv_bfloat16 hh[4], ll[4];
    const float f[4] = {acc.x, acc.y, acc.z, acc.w};
#pragma unroll
    for (int k = 0; k < 4; k++) {
        hh[k] = __float2bfloat16(f[k]);
        ll[k] = __float2bfloat16(f[k] - __bfloat162float(hh[k]));
    }
    __nv_bfloat16* base = outCat + (size_t)bq * KP2 + h * 32 + c4 * 4;
    *(uint2*)(base)       = *(const uint2*)hh;
    *(uint2*)(base + 256) = *(const uint2*)ll;
}

// ---------------------------------------------------------------------------
// Launch
// ---------------------------------------------------------------------------
extern "C" void kernel_launch(void* const* d_in, const int* in_sizes, int n_in,
                              void* d_out, int out_size)
{
    const float* query  = (const float*)d_in[0];
    const float* value  = (const float*)d_in[1];
    const float* refp   = (const float*)d_in[2];
    const int*   shapes = (const int*)  d_in[3];
    const int*   starts = (const int*)  d_in[4];
    const float* Wv  = (const float*)d_in[5];
    const float* bv  = (const float*)d_in[6];
    const float* Wso = (const float*)d_in[7];
    const float* bso = (const float*)d_in[8];
    const float* Waw = (const float*)d_in[9];
    const float* baw = (const float*)d_in[10];
    const float* Wo  = (const float*)d_in[11];
    const float* bo  = (const float*)d_in[12];
    float* out = (float*)d_out;

    const int M = in_sizes[0] / EDIM;   // 40394

    float *pQA, *pBiasQA;
    __half* pVh;
    __nv_bfloat16 *pAval, *pAq, *pAtmp, *pBv, *pBqa, *pBo;
    cudaGetSymbolAddress((void**)&pVh,    g_Vh);
    cudaGetSymbolAddress((void**)&pQA,    g_QA);
    cudaGetSymbolAddress((void**)&pBiasQA,g_biasQA);
    cudaGetSymbolAddress((void**)&pAval,  g_Aval);
    cudaGetSymbolAddress((void**)&pAq,    g_Aq);
    cudaGetSymbolAddress((void**)&pAtmp,  g_Atmp);
    cudaGetSymbolAddress((void**)&pBv,    g_Bv);
    cudaGetSymbolAddress((void**)&pBqa,   g_Bqa);
    cudaGetSymbolAddress((void**)&pBo,    g_Bo);

    cudaFuncSetAttribute(gemm_vqa, cudaFuncAttributeMaxDynamicSharedMemorySize, SMEM_GEMM);
    cudaFuncSetAttribute(gemm_out, cudaFuncAttributeMaxDynamicSharedMemorySize, SMEM_GEMM);

    const int n4 = M * (EDIM / 4);
    const int cvtB = (n4 + 255) / 256;
    const int wB   = (229760 + 255) / 256;
    const int mTiles = (M + 127) / 128;
    const int nTout = 2 * mTiles;                 // 632
    const int gOut  = nTout > 592 ? 592 : nTout;

    prep_all<<<2 * cvtB + wB, 256>>>(value, query, Wv, Wso, Waw, Wo, bso, baw,
                                     n4, cvtB);
    gemm_vqa<<<dim3(mTiles, 5), 256, SMEM_GEMM>>>(
        pAval, pBv, bv, pVh, pAq, pBqa, pBiasQA, pQA, M);
    msda_sample4<<<(M + 3) / 4, 256>>>(pVh, pQA, refp, shapes, starts, pAtmp, M);
    gemm_out<<<gOut, 256, SMEM_GEMM>>>(pAtmp, pBo, bo, query, out, M, nTout);
}

// round 15
// speedup vs baseline: 1.1623x; 1.0024x over previous
#include <cuda_runtime.h>
#include <cuda_bf16.h>
#include <cuda_fp16.h>
#include <math.h>
#include <stdint.h>

// ---------------------------------------------------------------------------
// MultiScaleDeformableAttention, fp32 in/out.
// GEMMs: mma.sync bf16 m16n8k16. Value & output GEMMs: 3-term compensation;
// QA GEMM: 1-term. V stored fp16 for the sampler.
// Round-15: GEMM tile BN 128->64 (warp tile 32x32, ~80 regs) + 2-stage
// pipeline (27.6KB/stage) -> 3 CTAs / 24 warps per SM to break the
// latency-bound plateau (all pipes were <40% at 16 warps).
// ---------------------------------------------------------------------------

#define NQ    20197
#define BSZ   2
#define EDIM  256
#define NLVL  4
#define MTOT  (BSZ * NQ)     // 40394

#define KP2   512            // [hi(256) | lo(256)] row stride
#define BK    32
#define NKIT  8              // 256 / BK
#define APAD2 72             // stage row elems (64 data + 8 pad)
#define TILE_AE (128 * APAD2)          // A tile elems per stage
#define TILE_BE (64 * APAD2)           // B tile elems per stage (BN=64)
#define STAGE_B ((TILE_AE + TILE_BE) * 2)   // 27648 B per stage
#define SMEM_GEMM (2 * STAGE_B)             // 55296 B -> 3 CTAs/SM

#define QASTR 384            // fused SO|AW output row stride

// ------------------------------- scratch ------------------------------------
__device__ __half g_Vh [MTOT * EDIM];           // projected value, fp16
__device__ float  g_QA [(size_t)MTOT * QASTR];  // [SO(256) | AWL(128)]
__device__ __nv_bfloat16 g_Aval[(size_t)MTOT * KP2];
__device__ __nv_bfloat16 g_Aq  [(size_t)MTOT * KP2];
__device__ __nv_bfloat16 g_Atmp[(size_t)MTOT * KP2];
__device__ __nv_bfloat16 g_Bv [256 * KP2];
__device__ __nv_bfloat16 g_Bqa[QASTR * KP2];
__device__ __nv_bfloat16 g_Bo [256 * KP2];
__device__ float g_biasQA[QASTR];

// -------------------------- small PTX helpers -------------------------------
__device__ __forceinline__ uint32_t smem_u32(const void* p) {
    uint32_t a;
    asm("{ .reg .u64 t; cvta.to.shared.u64 t, %1; cvt.u32.u64 %0, t; }"
        : "=r"(a) : "l"(p));
    return a;
}
__device__ __forceinline__ void cp_async16(uint32_t dst, const void* src) {
    asm volatile("cp.async.cg.shared.global [%0], [%1], 16;"
                 :: "r"(dst), "l"(src) : "memory");
}
__device__ __forceinline__ void cp_commit() {
    asm volatile("cp.async.commit_group;" ::: "memory");
}
template <int N>
__device__ __forceinline__ void cp_wait() {
    asm volatile("cp.async.wait_group %0;" :: "n"(N) : "memory");
}
__device__ __forceinline__ void ldmatrix_x4(uint32_t* r, uint32_t addr) {
    asm volatile("ldmatrix.sync.aligned.m8n8.x4.shared.b16 {%0,%1,%2,%3}, [%4];"
                 : "=r"(r[0]), "=r"(r[1]), "=r"(r[2]), "=r"(r[3]) : "r"(addr));
}
__device__ __forceinline__ void mma_bf16(float* c, const uint32_t* a,
                                         uint32_t b0, uint32_t b1) {
    asm volatile(
        "mma.sync.aligned.m16n8k16.row.col.f32.bf16.bf16.f32 "
        "{%0,%1,%2,%3}, {%4,%5,%6,%7}, {%8,%9}, {%0,%1,%2,%3};"
        : "+f"(c[0]), "+f"(c[1]), "+f"(c[2]), "+f"(c[3])
        : "r"(a[0]), "r"(a[1]), "r"(a[2]), "r"(a[3]), "r"(b0), "r"(b1));
}

// ---------------------------------------------------------------------------
// Merged conversion kernel. Query writes hi ONLY (QA GEMM is 1-term).
// ---------------------------------------------------------------------------
__global__ __launch_bounds__(256) void prep_all(
    const float* __restrict__ value, const float* __restrict__ query,
    const float* __restrict__ Wv,  const float* __restrict__ Wso,
    const float* __restrict__ Waw, const float* __restrict__ Wo,
    const float* __restrict__ bso, const float* __restrict__ baw,
    int n4, int cvtB)
{
    const int bx  = blockIdx.x;
    const int tid = threadIdx.x;

    if (bx < 2 * cvtB) {
        const bool isVal = (bx < cvtB);
        const float* x = isVal ? value : query;
        __nv_bfloat16* out = isVal ? g_Aval : g_Aq;
        const int i = (bx % cvtB) * 256 + tid;
        if (i >= n4) return;
        const float4 v = ((const float4*)x)[i];
        const int row = i >> 6;
        const int c4  = (i & 63) << 2;
        __nv_bfloat16 h[4], l[4];
        const float f[4] = {v.x, v.y, v.z, v.w};
#pragma unroll
        for (int k = 0; k < 4; k++) {
            h[k] = __float2bfloat16(f[k]);
            l[k] = __float2bfloat16(f[k] - __bfloat162float(h[k]));
        }
        __nv_bfloat16* base = out + (size_t)row * KP2 + c4;
        *(uint2*)(base) = *(const uint2*)h;
        if (isVal)
            *(uint2*)(base + 256) = *(const uint2*)l;
        return;
    }

    const int idx = (bx - 2 * cvtB) * 256 + tid;
    const float* W;
    __nv_bfloat16* Bt;
    int li, N, nofs = 0;
    if (idx < 65536)        { W = Wv;  Bt = g_Bv;  li = idx;          N = 256; }
    else if (idx < 131072)  { W = Wso; Bt = g_Bqa; li = idx - 65536;  N = 256; }
    else if (idx < 163840)  { W = Waw; Bt = g_Bqa; li = idx - 131072; N = 128; nofs = 256; }
    else if (idx < 229376)  { W = Wo;  Bt = g_Bo;  li = idx - 163840; N = 256; }
    else {
        const int i = idx - 229376;
        if (i < 256)      g_biasQA[i] = bso[i];
        else if (i < 384) g_biasQA[i] = baw[i - 256];
        return;
    }
    const int k = li / N, n = li % N;
    const float v = W[li];
    const __nv_bfloat16 h = __float2bfloat16(v);
    const __nv_bfloat16 l = __float2bfloat16(v - __bfloat162float(h));
    __nv_bfloat16* base = Bt + (size_t)(n + nofs) * KP2 + k;
    base[0]   = h;
    base[256] = l;
}

// ---------------------------------------------------------------------------
// GEMM core: BM=128, BN=64, BK=32, 8 warps (4x2), warp tile 32x32.
// 2-stage cp.async (prefetch distance 1, one sync per k-iter).
// nterms=3: full compensation; nterms=1: Ah*Bh only.
// If Ch != nullptr: epilogue writes fp16 to Ch (row stride 256, no residual).
// ---------------------------------------------------------------------------
__device__ __forceinline__ void gemm_body(
    const __nv_bfloat16* __restrict__ A, const __nv_bfloat16* __restrict__ Bt,
    const float* __restrict__ bias, const float* __restrict__ res,
    float* __restrict__ C, __half* __restrict__ Ch,
    int M, int N, int m0, int n0, char* smem, int nterms)
{
    const uint32_t sBase = smem_u32(smem);
    const int tid  = threadIdx.x;
    const int lane = tid & 31;
    const int wid  = tid >> 5;
    const int wm   = wid & 3;      // 4 warps along M (32 rows each)
    const int wn   = wid >> 2;     // 2 warps along N (32 cols each)

    // stage chunks: A = 1024 x 16B, B = 512 x 16B -> 6 chunks/thread
    auto load_stage = [&](int stg, int kt) {
        const int kbase = kt * BK;
        const uint32_t sA = sBase + (uint32_t)stg * STAGE_B;
        const uint32_t sB = sA + TILE_AE * 2;
#pragma unroll
        for (int it = 0; it < 6; it++) {
            const int c = tid + it * 256;          // 0..1535
            const bool isA = (c < 1024);
            const int cc  = isA ? c : (c - 1024);
            const int row = cc >> 3;
            const int seg = (cc & 7) << 3;
            if (nterms == 1 && seg >= 32) continue;   // skip lo halves
            const int gcol = (seg < 32) ? (kbase + seg) : (256 + kbase + seg - 32);
            const uint32_t soff = (uint32_t)(row * APAD2 + seg) * 2;
            if (isA) {
                const int ar = min(m0 + row, M - 1);
                cp_async16(sA + soff, A + (size_t)ar * KP2 + gcol);
            } else {
                cp_async16(sB + soff, Bt + (size_t)(n0 + row) * KP2 + gcol);
            }
        }
    };

    float acc[2][4][4];
#pragma unroll
    for (int mi = 0; mi < 2; mi++)
#pragma unroll
        for (int nj = 0; nj < 4; nj++)
#pragma unroll
            for (int k = 0; k < 4; k++) acc[mi][nj][k] = 0.f;

    load_stage(0, 0); cp_commit();

    int stg = 0;
#pragma unroll 1
    for (int kt = 0; kt < NKIT; kt++) {
        cp_wait<0>();
        __syncthreads();

        if (kt + 1 < NKIT) { load_stage(stg ^ 1, kt + 1); cp_commit(); }

        const uint32_t aB = sBase + (uint32_t)stg * STAGE_B;
        const uint32_t bB = aB + TILE_AE * 2;

#pragma unroll
        for (int ks = 0; ks < 2; ks++) {
            uint32_t ah[2][4], al[2][4];
#pragma unroll
            for (int mi = 0; mi < 2; mi++) {
                const int row = wm * 32 + mi * 16 + (lane & 15);
                const int col = ks * 16 + ((lane >> 4) << 3);
                ldmatrix_x4(ah[mi], aB + (uint32_t)(row * APAD2 + col) * 2);
                if (nterms == 3)
                    ldmatrix_x4(al[mi], aB + (uint32_t)(row * APAD2 + 32 + col) * 2);
            }
#pragma unroll
            for (int njp = 0; njp < 2; njp++) {
                const int row = wn * 32 + njp * 16 + ((lane >> 4) & 1) * 8 + (lane & 7);
                const int col = ks * 16 + ((lane >> 3) & 1) * 8;
                uint32_t bh[4], bl[4];
                ldmatrix_x4(bh, bB + (uint32_t)(row * APAD2 + col) * 2);
                if (nterms == 3)
                    ldmatrix_x4(bl, bB + (uint32_t)(row * APAD2 + 32 + col) * 2);

                float* a00 = acc[0][njp * 2];
                float* a01 = acc[0][njp * 2 + 1];
                float* a10 = acc[1][njp * 2];
                float* a11 = acc[1][njp * 2 + 1];

                mma_bf16(a00, ah[0], bh[0], bh[1]);
                mma_bf16(a01, ah[0], bh[2], bh[3]);
                mma_bf16(a10, ah[1], bh[0], bh[1]);
                mma_bf16(a11, ah[1], bh[2], bh[3]);
                if (nterms == 3) {
                    mma_bf16(a00, ah[0], bl[0], bl[1]);
                    mma_bf16(a01, ah[0], bl[2], bl[3]);
                    mma_bf16(a10, ah[1], bl[0], bl[1]);
                    mma_bf16(a11, ah[1], bl[2], bl[3]);
                    mma_bf16(a00, al[0], bh[0], bh[1]);
                    mma_bf16(a01, al[0], bh[2], bh[3]);
                    mma_bf16(a10, al[1], bh[0], bh[1]);
                    mma_bf16(a11, al[1], bh[2], bh[3]);
                }
            }
        }
        stg ^= 1;
    }

#pragma unroll
    for (int mi = 0; mi < 2; mi++) {
#pragma unroll
        for (int nj = 0; nj < 4; nj++) {
            const int col = n0 + wn * 32 + nj * 8 + (lane & 3) * 2;
            const int r0  = m0 + wm * 32 + mi * 16 + (lane >> 2);
            const int r1  = r0 + 8;
            const float b0 = bias[col], b1 = bias[col + 1];
            if (Ch) {
                if (r0 < M)
                    *(__half2*)(Ch + (size_t)r0 * 256 + col) =
                        __floats2half2_rn(acc[mi][nj][0] + b0, acc[mi][nj][1] + b1);
                if (r1 < M)
                    *(__half2*)(Ch + (size_t)r1 * 256 + col) =
                        __floats2half2_rn(acc[mi][nj][2] + b0, acc[mi][nj][3] + b1);
            } else {
                if (r0 < M) {
                    float2 o = make_float2(acc[mi][nj][0] + b0, acc[mi][nj][1] + b1);
                    if (res) {
                        const float2 rv = *(const float2*)(res + (size_t)r0 * N + col);
                        o.x += rv.x; o.y += rv.y;
                    }
                    *(float2*)(C + (size_t)r0 * N + col) = o;
                }
                if (r1 < M) {
                    float2 o = make_float2(acc[mi][nj][2] + b0, acc[mi][nj][3] + b1);
                    if (res) {
                        const float2 rv = *(const float2*)(res + (size_t)r1 * N + col);
                        o.x += rv.x; o.y += rv.y;
                    }
                    *(float2*)(C + (size_t)r1 * N + col) = o;
                }
            }
        }
    }
}

// Fused value+QA GEMM: y 0-3 -> value (3-term, fp16 out, 64-col slabs),
// y 4-9 -> QA (1-term, 64-col slabs of the 384-wide output).
__global__ __launch_bounds__(256, 3) void gemm_vqa(
    const __nv_bfloat16* __restrict__ Av, const __nv_bfloat16* __restrict__ Bv,
    const float* __restrict__ bv, __half* __restrict__ Vh,
    const __nv_bfloat16* __restrict__ Aq, const __nv_bfloat16* __restrict__ Bqa,
    const float* __restrict__ bqa, float* __restrict__ Cqa, int M)
{
    extern __shared__ __align__(16) char smem[];
    const int y = blockIdx.y;
    const int m0 = blockIdx.x * 128;
    if (y < 4)
        gemm_body(Av, Bv, bv, nullptr, nullptr, Vh, M, 256, m0, y * 64, smem, 3);
    else
        gemm_body(Aq, Bqa, bqa, nullptr, Cqa, nullptr, M, QASTR, m0,
                  (y - 4) * 64, smem, 1);
}

// Output GEMM: tile t -> m = t>>2, n = (t&3)*64 (4 consecutive blocks share A).
__global__ __launch_bounds__(256, 3) void gemm_out(
    const __nv_bfloat16* __restrict__ A, const __nv_bfloat16* __restrict__ Bt,
    const float* __restrict__ bias, const float* __restrict__ res,
    float* __restrict__ C, int M)
{
    extern __shared__ __align__(16) char smem[];
    const int t = blockIdx.x;
    gemm_body(A, Bt, bias, res, C, nullptr, M, 256,
              (t >> 2) * 128, (t & 3) * 64, smem, 3);
}

// ---------------------------------------------------------------------------
// Sampler (R14: fp16 V, block = 4 queries, 8 lanes x uint2 per head).
// ---------------------------------------------------------------------------
__global__ __launch_bounds__(256) void msda_sample4(
    const __half* __restrict__ V, const float* __restrict__ QA,
    const float* __restrict__ refp,
    const int* __restrict__ shapes, const int* __restrict__ starts,
    __nv_bfloat16* __restrict__ outCat, int M)
{
    __shared__ int4   sOff[4][16][8];
    __shared__ float4 sW  [4][16][8];

    const int tid = threadIdx.x;

    // Phase A
    {
        const int wi  = tid << 1;
        const int bqL = wi >> 7;
        const int h   = (wi >> 4) & 7;
        const int pt0 = wi & 15;
        int bq = blockIdx.x * 4 + bqL;
        bq = min(bq, M - 1);

        const float2 lg = *(const float2*)(QA + (size_t)bq * QASTR + 256 + h * 16 + pt0);
        float mx = fmaxf(lg.x, lg.y);
#pragma unroll
        for (int off = 4; off; off >>= 1)
            mx = fmaxf(mx, __shfl_xor_sync(0xffffffffu, mx, off));
        const float e0 = expf(lg.x - mx);
        const float e1 = expf(lg.y - mx);
        float sm = e0 + e1;
#pragma unroll
        for (int off = 4; off; off >>= 1)
            sm += __shfl_xor_sync(0xffffffffu, sm, off);
        const float inv = 1.f / sm;

        const int l = pt0 >> 2;
        const int H = shapes[2 * l + 0];
        const int W = shapes[2 * l + 1];
        const int st = starts[l];
        const float2 rp = *(const float2*)(refp + ((size_t)bq * NLVL + l) * 2);
        const float4 so = *(const float4*)(QA + (size_t)bq * QASTR + h * 32 + pt0 * 2);

#pragma unroll
        for (int k = 0; k < 2; k++) {
            const int pt = pt0 + k;
            const float aw  = (k ? e1 : e0) * inv;
            const float sox = k ? so.z : so.x;
            const float soy = k ? so.w : so.y;

            const float x = fmaf(rp.x, (float)W, sox) - 0.5f;
            const float y = fmaf(rp.y, (float)H, soy) - 0.5f;
            const float xf = floorf(x), yf = floorf(y);
            const int x0 = (int)xf, y0 = (int)yf;
            const float wx1 = x - xf, wx0 = 1.f - wx1;
            const float wy1 = y - yf, wy0 = 1.f - wy1;

            const bool vx0 = (x0 >= 0) && (x0 < W);
            const bool vx1 = (x0 + 1 >= 0) && (x0 + 1 < W);
            const bool vy0 = (y0 >= 0) && (y0 < H);
            const bool vy1 = (y0 + 1 >= 0) && (y0 + 1 < H);

            const int cx0 = max(0, min(x0,     W - 1));
            const int cx1 = max(0, min(x0 + 1, W - 1));
            const int cy0 = max(0, min(y0,     H - 1));
            const int cy1 = max(0, min(y0 + 1, H - 1));

            int4 o;
            o.x = st + cy0 * W + cx0;
            o.y = st + cy0 * W + cx1;
            o.z = st + cy1 * W + cx0;
            o.w = st + cy1 * W + cx1;

            float4 w4;
            w4.x = (vx0 && vy0) ? wx0 * wy0 * aw : 0.f;
            w4.y = (vx1 && vy0) ? wx1 * wy0 * aw : 0.f;
            w4.z = (vx0 && vy1) ? wx0 * wy1 * aw : 0.f;
            w4.w = (vx1 && vy1) ? wx1 * wy1 * aw : 0.f;

            sOff[bqL][pt][h] = o;
            sW  [bqL][pt][h] = w4;
        }
    }
    __syncthreads();

    // Phase B: warp = (q, head-pair); 8 lanes x uint2 per head.
    const int warpId = tid >> 5;
    const int lane   = tid & 31;
    const int bqL    = warpId >> 1;
    const int h      = ((warpId & 1) << 2) + (lane >> 3);
    const int c4     = lane & 7;
    const int bq     = blockIdx.x * 4 + bqL;
    if (bq >= M) return;
    const int b = bq / NQ;

    const __half* vb = V + (size_t)b * NQ * EDIM + h * 32 + c4 * 4;

    float4 acc = make_float4(0.f, 0.f, 0.f, 0.f);
#pragma unroll
    for (int pt = 0; pt < 16; pt++) {
        const int4   o = sOff[bqL][pt][h];
        const float4 w = sW  [bqL][pt][h];

        const uint2 u0 = *(const uint2*)(vb + (size_t)o.x * EDIM);
        const uint2 u1 = *(const uint2*)(vb + (size_t)o.y * EDIM);
        const uint2 u2 = *(const uint2*)(vb + (size_t)o.z * EDIM);
        const uint2 u3 = *(const uint2*)(vb + (size_t)o.w * EDIM);

        const float2 p00 = __half22float2(*(const __half2*)&u0.x);
        const float2 p01 = __half22float2(*(const __half2*)&u0.y);
        const float2 p10 = __half22float2(*(const __half2*)&u1.x);
        const float2 p11 = __half22float2(*(const __half2*)&u1.y);
        const float2 p20 = __half22float2(*(const __half2*)&u2.x);
        const float2 p21 = __half22float2(*(const __half2*)&u2.y);
        const float2 p30 = __half22float2(*(const __half2*)&u3.x);
        const float2 p31 = __half22float2(*(const __half2*)&u3.y);

        acc.x = fmaf(w.x, p00.x, acc.x); acc.y = fmaf(w.x, p00.y, acc.y);
        acc.z = fmaf(w.x, p01.x, acc.z); acc.w = fmaf(w.x, p01.y, acc.w);
        acc.x = fmaf(w.y, p10.x, acc.x); acc.y = fmaf(w.y, p10.y, acc.y);
        acc.z = fmaf(w.y, p11.x, acc.z); acc.w = fmaf(w.y, p11.y, acc.w);
        acc.x = fmaf(w.z, p20.x, acc.x); acc.y = fmaf(w.z, p20.y, acc.y);
        acc.z = fmaf(w.z, p21.x, acc.z); acc.w = fmaf(w.z, p21.y, acc.w);
        acc.x = fmaf(w.w, p30.x, acc.x); acc.y = fmaf(w.w, p30.y, acc.y);
        acc.z = fmaf(w.w, p31.x, acc.z); acc.w = fmaf(w.w, p31.y, acc.w);
    }

    __nv_bfloat16 hh[4], ll[4];
    const float f[4] = {acc.x, acc.y, acc.z, acc.w};
#pragma unroll
    for (int k = 0; k < 4; k++) {
        hh[k] = __float2bfloat16(f[k]);
        ll[k] = __float2bfloat16(f[k] - __bfloat162float(hh[k]));
    }
    __nv_bfloat16* base = outCat + (size_t)bq * KP2 + h * 32 + c4 * 4;
    *(uint2*)(base)       = *(const uint2*)hh;
    *(uint2*)(base + 256) = *(const uint2*)ll;
}

// ---------------------------------------------------------------------------
// Launch
// ---------------------------------------------------------------------------
extern "C" void kernel_launch(void* const* d_in, const int* in_sizes, int n_in,
                              void* d_out, int out_size)
{
    const float* query  = (const float*)d_in[0];
    const float* value  = (const float*)d_in[1];
    const float* refp   = (const float*)d_in[2];
    const int*   shapes = (const int*)  d_in[3];
    const int*   starts = (const int*)  d_in[4];
    const float* Wv  = (const float*)d_in[5];
    const float* bv  = (const float*)d_in[6];
    const float* Wso = (const float*)d_in[7];
    const float* bso = (const float*)d_in[8];
    const float* Waw = (const float*)d_in[9];
    const float* baw = (const float*)d_in[10];
    const float* Wo  = (const float*)d_in[11];
    const float* bo  = (const float*)d_in[12];
    float* out = (float*)d_out;

    const int M = in_sizes[0] / EDIM;   // 40394

    float *pQA, *pBiasQA;
    __half* pVh;
    __nv_bfloat16 *pAval, *pAq, *pAtmp, *pBv, *pBqa, *pBo;
    cudaGetSymbolAddress((void**)&pVh,    g_Vh);
    cudaGetSymbolAddress((void**)&pQA,    g_QA);
    cudaGetSymbolAddress((void**)&pBiasQA,g_biasQA);
    cudaGetSymbolAddress((void**)&pAval,  g_Aval);
    cudaGetSymbolAddress((void**)&pAq,    g_Aq);
    cudaGetSymbolAddress((void**)&pAtmp,  g_Atmp);
    cudaGetSymbolAddress((void**)&pBv,    g_Bv);
    cudaGetSymbolAddress((void**)&pBqa,   g_Bqa);
    cudaGetSymbolAddress((void**)&pBo,    g_Bo);

    cudaFuncSetAttribute(gemm_vqa, cudaFuncAttributeMaxDynamicSharedMemorySize, SMEM_GEMM);
    cudaFuncSetAttribute(gemm_out, cudaFuncAttributeMaxDynamicSharedMemorySize, SMEM_GEMM);

    const int n4 = M * (EDIM / 4);
    const int cvtB = (n4 + 255) / 256;
    const int wB   = (229760 + 255) / 256;
    const int mTiles = (M + 127) / 128;   // 316

    prep_all<<<2 * cvtB + wB, 256>>>(value, query, Wv, Wso, Waw, Wo, bso, baw,
                                     n4, cvtB);
    gemm_vqa<<<dim3(mTiles, 10), 256, SMEM_GEMM>>>(
        pAval, pBv, bv, pVh, pAq, pBqa, pBiasQA, pQA, M);
    msda_sample4<<<(M + 3) / 4, 256>>>(pVh, pQA, refp, shapes, starts, pAtmp, M);
    gemm_out<<<mTiles * 4, 256, SMEM_GEMM>>>(pAtmp, pBo, bo, query, out, M);
}

// round 16
// speedup vs baseline: 1.1843x; 1.0189x over previous
#include <cuda_runtime.h>
#include <cuda_bf16.h>
#include <cuda_fp16.h>
#include <math.h>
#include <stdint.h>

// ---------------------------------------------------------------------------
// MultiScaleDeformableAttention, fp32 in/out.
// GEMMs: mma.sync bf16 m16n8k16, 3-term compensation (value/output),
// 1-term (QA). V stored fp16 for the sampler.
// Round-16: per-GEMM tile selection --
//   gemm_vqa: WIDE body (BM=128,BN=128, 3-stage, 2 CTAs/SM)  [R14 best]
//   gemm_out: NARROW body (BM=128,BN=64, 2-stage, 3 CTAs/SM) [R15 best]
// ---------------------------------------------------------------------------

#define NQ    20197
#define BSZ   2
#define EDIM  256
#define NLVL  4
#define MTOT  (BSZ * NQ)     // 40394

#define KP2   512            // [hi(256) | lo(256)] row stride
#define BK    32
#define NKIT  8              // 256 / BK
#define APAD2 72             // stage row elems (64 data + 8 pad)

// wide (vqa): A 128 rows + B 128 rows per stage
#define TILE_WE (128 * APAD2)
#define STAGE_W (2 * TILE_WE * 2)        // 36864 B
#define SMEM_W  (3 * STAGE_W)            // 110592 B -> 2 CTAs/SM

// narrow (out): A 128 rows + B 64 rows per stage
#define TILE_AE (128 * APAD2)
#define TILE_BE (64 * APAD2)
#define STAGE_N ((TILE_AE + TILE_BE) * 2)  // 27648 B
#define SMEM_N  (2 * STAGE_N)              // 55296 B -> 3 CTAs/SM

#define QASTR 384            // fused SO|AW output row stride

// ------------------------------- scratch ------------------------------------
__device__ __half g_Vh [MTOT * EDIM];           // projected value, fp16
__device__ float  g_QA [(size_t)MTOT * QASTR];  // [SO(256) | AWL(128)]
__device__ __nv_bfloat16 g_Aval[(size_t)MTOT * KP2];
__device__ __nv_bfloat16 g_Aq  [(size_t)MTOT * KP2];
__device__ __nv_bfloat16 g_Atmp[(size_t)MTOT * KP2];
__device__ __nv_bfloat16 g_Bv [256 * KP2];
__device__ __nv_bfloat16 g_Bqa[QASTR * KP2];
__device__ __nv_bfloat16 g_Bo [256 * KP2];
__device__ float g_biasQA[QASTR];

// -------------------------- small PTX helpers -------------------------------
__device__ __forceinline__ uint32_t smem_u32(const void* p) {
    uint32_t a;
    asm("{ .reg .u64 t; cvta.to.shared.u64 t, %1; cvt.u32.u64 %0, t; }"
        : "=r"(a) : "l"(p));
    return a;
}
__device__ __forceinline__ void cp_async16(uint32_t dst, const void* src) {
    asm volatile("cp.async.cg.shared.global [%0], [%1], 16;"
                 :: "r"(dst), "l"(src) : "memory");
}
__device__ __forceinline__ void cp_commit() {
    asm volatile("cp.async.commit_group;" ::: "memory");
}
template <int N>
__device__ __forceinline__ void cp_wait() {
    asm volatile("cp.async.wait_group %0;" :: "n"(N) : "memory");
}
__device__ __forceinline__ void ldmatrix_x4(uint32_t* r, uint32_t addr) {
    asm volatile("ldmatrix.sync.aligned.m8n8.x4.shared.b16 {%0,%1,%2,%3}, [%4];"
                 : "=r"(r[0]), "=r"(r[1]), "=r"(r[2]), "=r"(r[3]) : "r"(addr));
}
__device__ __forceinline__ void mma_bf16(float* c, const uint32_t* a,
                                         uint32_t b0, uint32_t b1) {
    asm volatile(
        "mma.sync.aligned.m16n8k16.row.col.f32.bf16.bf16.f32 "
        "{%0,%1,%2,%3}, {%4,%5,%6,%7}, {%8,%9}, {%0,%1,%2,%3};"
        : "+f"(c[0]), "+f"(c[1]), "+f"(c[2]), "+f"(c[3])
        : "r"(a[0]), "r"(a[1]), "r"(a[2]), "r"(a[3]), "r"(b0), "r"(b1));
}

// ---------------------------------------------------------------------------
// Merged conversion kernel. Query writes hi ONLY (QA GEMM is 1-term).
// ---------------------------------------------------------------------------
__global__ __launch_bounds__(256) void prep_all(
    const float* __restrict__ value, const float* __restrict__ query,
    const float* __restrict__ Wv,  const float* __restrict__ Wso,
    const float* __restrict__ Waw, const float* __restrict__ Wo,
    const float* __restrict__ bso, const float* __restrict__ baw,
    int n4, int cvtB)
{
    const int bx  = blockIdx.x;
    const int tid = threadIdx.x;

    if (bx < 2 * cvtB) {
        const bool isVal = (bx < cvtB);
        const float* x = isVal ? value : query;
        __nv_bfloat16* out = isVal ? g_Aval : g_Aq;
        const int i = (bx % cvtB) * 256 + tid;
        if (i >= n4) return;
        const float4 v = ((const float4*)x)[i];
        const int row = i >> 6;
        const int c4  = (i & 63) << 2;
        __nv_bfloat16 h[4], l[4];
        const float f[4] = {v.x, v.y, v.z, v.w};
#pragma unroll
        for (int k = 0; k < 4; k++) {
            h[k] = __float2bfloat16(f[k]);
            l[k] = __float2bfloat16(f[k] - __bfloat162float(h[k]));
        }
        __nv_bfloat16* base = out + (size_t)row * KP2 + c4;
        *(uint2*)(base) = *(const uint2*)h;
        if (isVal)
            *(uint2*)(base + 256) = *(const uint2*)l;
        return;
    }

    const int idx = (bx - 2 * cvtB) * 256 + tid;
    const float* W;
    __nv_bfloat16* Bt;
    int li, N, nofs = 0;
    if (idx < 65536)        { W = Wv;  Bt = g_Bv;  li = idx;          N = 256; }
    else if (idx < 131072)  { W = Wso; Bt = g_Bqa; li = idx - 65536;  N = 256; }
    else if (idx < 163840)  { W = Waw; Bt = g_Bqa; li = idx - 131072; N = 128; nofs = 256; }
    else if (idx < 229376)  { W = Wo;  Bt = g_Bo;  li = idx - 163840; N = 256; }
    else {
        const int i = idx - 229376;
        if (i < 256)      g_biasQA[i] = bso[i];
        else if (i < 384) g_biasQA[i] = baw[i - 256];
        return;
    }
    const int k = li / N, n = li % N;
    const float v = W[li];
    const __nv_bfloat16 h = __float2bfloat16(v);
    const __nv_bfloat16 l = __float2bfloat16(v - __bfloat162float(h));
    __nv_bfloat16* base = Bt + (size_t)(n + nofs) * KP2 + k;
    base[0]   = h;
    base[256] = l;
}

// ---------------------------------------------------------------------------
// WIDE GEMM body (R14): BM=128, BN=128, BK=32, 3-stage, warp tile 32x64.
// ---------------------------------------------------------------------------
__device__ __forceinline__ void gemm_body_w(
    const __nv_bfloat16* __restrict__ A, const __nv_bfloat16* __restrict__ Bt,
    const float* __restrict__ bias, float* __restrict__ C,
    __half* __restrict__ Ch, int M, int N, int m0, int n0, char* smem,
    int nterms)
{
    const uint32_t sBase = smem_u32(smem);
    const int tid  = threadIdx.x;
    const int lane = tid & 31;
    const int wid  = tid >> 5;
    const int wm   = wid & 3;
    const int wn   = wid >> 2;

    auto load_stage = [&](int stg, int kt) {
        const int kbase = kt * BK;
        const uint32_t sA = sBase + (uint32_t)stg * STAGE_W;
        const uint32_t sB = sA + TILE_WE * 2;
#pragma unroll
        for (int it = 0; it < 4; it++) {
            const int c   = tid + it * 256;
            const int row = c >> 3;
            const int seg = (c & 7) << 3;
            if (nterms == 1 && seg >= 32) continue;
            const int gcol = (seg < 32) ? (kbase + seg) : (256 + kbase + seg - 32);
            const uint32_t soff = (uint32_t)(row * APAD2 + seg) * 2;
            const int ar = min(m0 + row, M - 1);
            cp_async16(sA + soff, A + (size_t)ar * KP2 + gcol);
            cp_async16(sB + soff, Bt + (size_t)(n0 + row) * KP2 + gcol);
        }
    };

    float acc[2][8][4];
#pragma unroll
    for (int mi = 0; mi < 2; mi++)
#pragma unroll
        for (int nj = 0; nj < 8; nj++)
#pragma unroll
            for (int k = 0; k < 4; k++) acc[mi][nj][k] = 0.f;

    load_stage(0, 0); cp_commit();
    load_stage(1, 1); cp_commit();

    int stg = 0;
#pragma unroll 1
    for (int kt = 0; kt < NKIT; kt++) {
        cp_wait<1>();
        __syncthreads();

        if (kt + 2 < NKIT) load_stage((stg + 2) % 3, kt + 2);
        cp_commit();

        const uint32_t aB = sBase + (uint32_t)stg * STAGE_W;
        const uint32_t bB = aB + TILE_WE * 2;

#pragma unroll
        for (int ks = 0; ks < 2; ks++) {
            uint32_t ah[2][4], al[2][4];
#pragma unroll
            for (int mi = 0; mi < 2; mi++) {
                const int row = wm * 32 + mi * 16 + (lane & 15);
                const int col = ks * 16 + ((lane >> 4) << 3);
                ldmatrix_x4(ah[mi], aB + (uint32_t)(row * APAD2 + col) * 2);
                if (nterms == 3)
                    ldmatrix_x4(al[mi], aB + (uint32_t)(row * APAD2 + 32 + col) * 2);
            }
#pragma unroll
            for (int njp = 0; njp < 4; njp++) {
                const int row = wn * 64 + njp * 16 + ((lane >> 4) & 1) * 8 + (lane & 7);
                const int col = ks * 16 + ((lane >> 3) & 1) * 8;
                uint32_t bh[4], bl[4];
                ldmatrix_x4(bh, bB + (uint32_t)(row * APAD2 + col) * 2);
                if (nterms == 3)
                    ldmatrix_x4(bl, bB + (uint32_t)(row * APAD2 + 32 + col) * 2);

                float* a00 = acc[0][njp * 2];
                float* a01 = acc[0][njp * 2 + 1];
                float* a10 = acc[1][njp * 2];
                float* a11 = acc[1][njp * 2 + 1];

                mma_bf16(a00, ah[0], bh[0], bh[1]);
                mma_bf16(a01, ah[0], bh[2], bh[3]);
                mma_bf16(a10, ah[1], bh[0], bh[1]);
                mma_bf16(a11, ah[1], bh[2], bh[3]);
                if (nterms == 3) {
                    mma_bf16(a00, ah[0], bl[0], bl[1]);
                    mma_bf16(a01, ah[0], bl[2], bl[3]);
                    mma_bf16(a10, ah[1], bl[0], bl[1]);
                    mma_bf16(a11, ah[1], bl[2], bl[3]);
                    mma_bf16(a00, al[0], bh[0], bh[1]);
                    mma_bf16(a01, al[0], bh[2], bh[3]);
                    mma_bf16(a10, al[1], bh[0], bh[1]);
                    mma_bf16(a11, al[1], bh[2], bh[3]);
                }
            }
        }
        stg = (stg + 1) % 3;
    }

#pragma unroll
    for (int mi = 0; mi < 2; mi++) {
#pragma unroll
        for (int nj = 0; nj < 8; nj++) {
            const int col = n0 + wn * 64 + nj * 8 + (lane & 3) * 2;
            const int r0  = m0 + wm * 32 + mi * 16 + (lane >> 2);
            const int r1  = r0 + 8;
            const float b0 = bias[col], b1 = bias[col + 1];
            if (Ch) {
                if (r0 < M)
                    *(__half2*)(Ch + (size_t)r0 * 256 + col) =
                        __floats2half2_rn(acc[mi][nj][0] + b0, acc[mi][nj][1] + b1);
                if (r1 < M)
                    *(__half2*)(Ch + (size_t)r1 * 256 + col) =
                        __floats2half2_rn(acc[mi][nj][2] + b0, acc[mi][nj][3] + b1);
            } else {
                if (r0 < M)
                    *(float2*)(C + (size_t)r0 * N + col) =
                        make_float2(acc[mi][nj][0] + b0, acc[mi][nj][1] + b1);
                if (r1 < M)
                    *(float2*)(C + (size_t)r1 * N + col) =
                        make_float2(acc[mi][nj][2] + b0, acc[mi][nj][3] + b1);
            }
        }
    }
}

// ---------------------------------------------------------------------------
// NARROW GEMM body (R15): BM=128, BN=64, BK=32, 2-stage, warp tile 32x32.
// 3-term only; fp32 C with bias + residual.
// ---------------------------------------------------------------------------
__device__ __forceinline__ void gemm_body_n(
    const __nv_bfloat16* __restrict__ A, const __nv_bfloat16* __restrict__ Bt,
    const float* __restrict__ bias, const float* __restrict__ res,
    float* __restrict__ C, int M, int N, int m0, int n0, char* smem)
{
    const uint32_t sBase = smem_u32(smem);
    const int tid  = threadIdx.x;
    const int lane = tid & 31;
    const int wid  = tid >> 5;
    const int wm   = wid & 3;
    const int wn   = wid >> 2;

    auto load_stage = [&](int stg, int kt) {
        const int kbase = kt * BK;
        const uint32_t sA = sBase + (uint32_t)stg * STAGE_N;
        const uint32_t sB = sA + TILE_AE * 2;
#pragma unroll
        for (int it = 0; it < 6; it++) {
            const int c = tid + it * 256;
            const bool isA = (c < 1024);
            const int cc  = isA ? c : (c - 1024);
            const int row = cc >> 3;
            const int seg = (cc & 7) << 3;
            const int gcol = (seg < 32) ? (kbase + seg) : (256 + kbase + seg - 32);
            const uint32_t soff = (uint32_t)(row * APAD2 + seg) * 2;
            if (isA) {
                const int ar = min(m0 + row, M - 1);
                cp_async16(sA + soff, A + (size_t)ar * KP2 + gcol);
            } else {
                cp_async16(sB + soff, Bt + (size_t)(n0 + row) * KP2 + gcol);
            }
        }
    };

    float acc[2][4][4];
#pragma unroll
    for (int mi = 0; mi < 2; mi++)
#pragma unroll
        for (int nj = 0; nj < 4; nj++)
#pragma unroll
            for (int k = 0; k < 4; k++) acc[mi][nj][k] = 0.f;

    load_stage(0, 0); cp_commit();

    int stg = 0;
#pragma unroll 1
    for (int kt = 0; kt < NKIT; kt++) {
        cp_wait<0>();
        __syncthreads();

        if (kt + 1 < NKIT) { load_stage(stg ^ 1, kt + 1); cp_commit(); }

        const uint32_t aB = sBase + (uint32_t)stg * STAGE_N;
        const uint32_t bB = aB + TILE_AE * 2;

#pragma unroll
        for (int ks = 0; ks < 2; ks++) {
            uint32_t ah[2][4], al[2][4];
#pragma unroll
            for (int mi = 0; mi < 2; mi++) {
                const int row = wm * 32 + mi * 16 + (lane & 15);
                const int col = ks * 16 + ((lane >> 4) << 3);
                ldmatrix_x4(ah[mi], aB + (uint32_t)(row * APAD2 + col) * 2);
                ldmatrix_x4(al[mi], aB + (uint32_t)(row * APAD2 + 32 + col) * 2);
            }
#pragma unroll
            for (int njp = 0; njp < 2; njp++) {
                const int row = wn * 32 + njp * 16 + ((lane >> 4) & 1) * 8 + (lane & 7);
                const int col = ks * 16 + ((lane >> 3) & 1) * 8;
                uint32_t bh[4], bl[4];
                ldmatrix_x4(bh, bB + (uint32_t)(row * APAD2 + col) * 2);
                ldmatrix_x4(bl, bB + (uint32_t)(row * APAD2 + 32 + col) * 2);

                float* a00 = acc[0][njp * 2];
                float* a01 = acc[0][njp * 2 + 1];
                float* a10 = acc[1][njp * 2];
                float* a11 = acc[1][njp * 2 + 1];

                mma_bf16(a00, ah[0], bh[0], bh[1]);
                mma_bf16(a01, ah[0], bh[2], bh[3]);
                mma_bf16(a10, ah[1], bh[0], bh[1]);
                mma_bf16(a11, ah[1], bh[2], bh[3]);
                mma_bf16(a00, ah[0], bl[0], bl[1]);
                mma_bf16(a01, ah[0], bl[2], bl[3]);
                mma_bf16(a10, ah[1], bl[0], bl[1]);
                mma_bf16(a11, ah[1], bl[2], bl[3]);
                mma_bf16(a00, al[0], bh[0], bh[1]);
                mma_bf16(a01, al[0], bh[2], bh[3]);
                mma_bf16(a10, al[1], bh[0], bh[1]);
                mma_bf16(a11, al[1], bh[2], bh[3]);
            }
        }
        stg ^= 1;
    }

#pragma unroll
    for (int mi = 0; mi < 2; mi++) {
#pragma unroll
        for (int nj = 0; nj < 4; nj++) {
            const int col = n0 + wn * 32 + nj * 8 + (lane & 3) * 2;
            const int r0  = m0 + wm * 32 + mi * 16 + (lane >> 2);
            const int r1  = r0 + 8;
            const float b0 = bias[col], b1 = bias[col + 1];
            if (r0 < M) {
                float2 o = make_float2(acc[mi][nj][0] + b0, acc[mi][nj][1] + b1);
                const float2 rv = *(const float2*)(res + (size_t)r0 * N + col);
                o.x += rv.x; o.y += rv.y;
                *(float2*)(C + (size_t)r0 * N + col) = o;
            }
            if (r1 < M) {
                float2 o = make_float2(acc[mi][nj][2] + b0, acc[mi][nj][3] + b1);
                const float2 rv = *(const float2*)(res + (size_t)r1 * N + col);
                o.x += rv.x; o.y += rv.y;
                *(float2*)(C + (size_t)r1 * N + col) = o;
            }
        }
    }
}

// Fused value+QA GEMM (wide body): y 0-1 value (3-term, fp16 out), y 2-4 QA.
__global__ __launch_bounds__(256, 2) void gemm_vqa(
    const __nv_bfloat16* __restrict__ Av, const __nv_bfloat16* __restrict__ Bv,
    const float* __restrict__ bv, __half* __restrict__ Vh,
    const __nv_bfloat16* __restrict__ Aq, const __nv_bfloat16* __restrict__ Bqa,
    const float* __restrict__ bqa, float* __restrict__ Cqa, int M)
{
    extern __shared__ __align__(16) char smem[];
    const int y = blockIdx.y;
    const int m0 = blockIdx.x * 128;
    if (y < 2)
        gemm_body_w(Av, Bv, bv, nullptr, Vh, M, 256, m0, y * 128, smem, 3);
    else
        gemm_body_w(Aq, Bqa, bqa, Cqa, nullptr, M, QASTR, m0, (y - 2) * 128,
                    smem, 1);
}

// Output GEMM (narrow body): tile t -> m = t>>2, n = (t&3)*64.
__global__ __launch_bounds__(256, 3) void gemm_out(
    const __nv_bfloat16* __restrict__ A, const __nv_bfloat16* __restrict__ Bt,
    const float* __restrict__ bias, const float* __restrict__ res,
    float* __restrict__ C, int M)
{
    extern __shared__ __align__(16) char smem[];
    const int t = blockIdx.x;
    gemm_body_n(A, Bt, bias, res, C, M, 256, (t >> 2) * 128, (t & 3) * 64, smem);
}

// ---------------------------------------------------------------------------
// Sampler (fp16 V, block = 4 queries, 8 lanes x uint2 per head).
// ---------------------------------------------------------------------------
__global__ __launch_bounds__(256) void msda_sample4(
    const __half* __restrict__ V, const float* __restrict__ QA,
    const float* __restrict__ refp,
    const int* __restrict__ shapes, const int* __restrict__ starts,
    __nv_bfloat16* __restrict__ outCat, int M)
{
    __shared__ int4   sOff[4][16][8];
    __shared__ float4 sW  [4][16][8];

    const int tid = threadIdx.x;

    // Phase A
    {
        const int wi  = tid << 1;
        const int bqL = wi >> 7;
        const int h   = (wi >> 4) & 7;
        const int pt0 = wi & 15;
        int bq = blockIdx.x * 4 + bqL;
        bq = min(bq, M - 1);

        const float2 lg = *(const float2*)(QA + (size_t)bq * QASTR + 256 + h * 16 + pt0);
        float mx = fmaxf(lg.x, lg.y);
#pragma unroll
        for (int off = 4; off; off >>= 1)
            mx = fmaxf(mx, __shfl_xor_sync(0xffffffffu, mx, off));
        const float e0 = expf(lg.x - mx);
        const float e1 = expf(lg.y - mx);
        float sm = e0 + e1;
#pragma unroll
        for (int off = 4; off; off >>= 1)
            sm += __shfl_xor_sync(0xffffffffu, sm, off);
        const float inv = 1.f / sm;

        const int l = pt0 >> 2;
        const int H = shapes[2 * l + 0];
        const int W = shapes[2 * l + 1];
        const int st = starts[l];
        const float2 rp = *(const float2*)(refp + ((size_t)bq * NLVL + l) * 2);
        const float4 so = *(const float4*)(QA + (size_t)bq * QASTR + h * 32 + pt0 * 2);

#pragma unroll
        for (int k = 0; k < 2; k++) {
            const int pt = pt0 + k;
            const float aw  = (k ? e1 : e0) * inv;
            const float sox = k ? so.z : so.x;
            const float soy = k ? so.w : so.y;

            const float x = fmaf(rp.x, (float)W, sox) - 0.5f;
            const float y = fmaf(rp.y, (float)H, soy) - 0.5f;
            const float xf = floorf(x), yf = floorf(y);
            const int x0 = (int)xf, y0 = (int)yf;
            const float wx1 = x - xf, wx0 = 1.f - wx1;
            const float wy1 = y - yf, wy0 = 1.f - wy1;

            const bool vx0 = (x0 >= 0) && (x0 < W);
            const bool vx1 = (x0 + 1 >= 0) && (x0 + 1 < W);
            const bool vy0 = (y0 >= 0) && (y0 < H);
            const bool vy1 = (y0 + 1 >= 0) && (y0 + 1 < H);

            const int cx0 = max(0, min(x0,     W - 1));
            const int cx1 = max(0, min(x0 + 1, W - 1));
            const int cy0 = max(0, min(y0,     H - 1));
            const int cy1 = max(0, min(y0 + 1, H - 1));

            int4 o;
            o.x = st + cy0 * W + cx0;
            o.y = st + cy0 * W + cx1;
            o.z = st + cy1 * W + cx0;
            o.w = st + cy1 * W + cx1;

            float4 w4;
            w4.x = (vx0 && vy0) ? wx0 * wy0 * aw : 0.f;
            w4.y = (vx1 && vy0) ? wx1 * wy0 * aw : 0.f;
            w4.z = (vx0 && vy1) ? wx0 * wy1 * aw : 0.f;
            w4.w = (vx1 && vy1) ? wx1 * wy1 * aw : 0.f;

            sOff[bqL][pt][h] = o;
            sW  [bqL][pt][h] = w4;
        }
    }
    __syncthreads();

    // Phase B: warp = (q, head-pair); 8 lanes x uint2 per head.
    const int warpId = tid >> 5;
    const int lane   = tid & 31;
    const int bqL    = warpId >> 1;
    const int h      = ((warpId & 1) << 2) + (lane >> 3);
    const int c4     = lane & 7;
    const int bq     = blockIdx.x * 4 + bqL;
    if (bq >= M) return;
    const int b = bq / NQ;

    const __half* vb = V + (size_t)b * NQ * EDIM + h * 32 + c4 * 4;

    float4 acc = make_float4(0.f, 0.f, 0.f, 0.f);
#pragma unroll
    for (int pt = 0; pt < 16; pt++) {
        const int4   o = sOff[bqL][pt][h];
        const float4 w = sW  [bqL][pt][h];

        const uint2 u0 = *(const uint2*)(vb + (size_t)o.x * EDIM);
        const uint2 u1 = *(const uint2*)(vb + (size_t)o.y * EDIM);
        const uint2 u2 = *(const uint2*)(vb + (size_t)o.z * EDIM);
        const uint2 u3 = *(const uint2*)(vb + (size_t)o.w * EDIM);

        const float2 p00 = __half22float2(*(const __half2*)&u0.x);
        const float2 p01 = __half22float2(*(const __half2*)&u0.y);
        const float2 p10 = __half22float2(*(const __half2*)&u1.x);
        const float2 p11 = __half22float2(*(const __half2*)&u1.y);
        const float2 p20 = __half22float2(*(const __half2*)&u2.x);
        const float2 p21 = __half22float2(*(const __half2*)&u2.y);
        const float2 p30 = __half22float2(*(const __half2*)&u3.x);
        const float2 p31 = __half22float2(*(const __half2*)&u3.y);

        acc.x = fmaf(w.x, p00.x, acc.x); acc.y = fmaf(w.x, p00.y, acc.y);
        acc.z = fmaf(w.x, p01.x, acc.z); acc.w = fmaf(w.x, p01.y, acc.w);
        acc.x = fmaf(w.y, p10.x, acc.x); acc.y = fmaf(w.y, p10.y, acc.y);
        acc.z = fmaf(w.y, p11.x, acc.z); acc.w = fmaf(w.y, p11.y, acc.w);
        acc.x = fmaf(w.z, p20.x, acc.x); acc.y = fmaf(w.z, p20.y, acc.y);
        acc.z = fmaf(w.z, p21.x, acc.z); acc.w = fmaf(w.z, p21.y, acc.w);
        acc.x = fmaf(w.w, p30.x, acc.x); acc.y = fmaf(w.w, p30.y, acc.y);
        acc.z = fmaf(w.w, p31.x, acc.z); acc.w = fmaf(w.w, p31.y, acc.w);
    }

    __nv_bfloat16 hh[4], ll[4];
    const float f[4] = {acc.x, acc.y, acc.z, acc.w};
#pragma unroll
    for (int k = 0; k < 4; k++) {
        hh[k] = __float2bfloat16(f[k]);
        ll[k] = __float2bfloat16(f[k] - __bfloat162float(hh[k]));
    }
    __nv_bfloat16* base = outCat + (size_t)bq * KP2 + h * 32 + c4 * 4;
    *(uint2*)(base)       = *(const uint2*)hh;
    *(uint2*)(base + 256) = *(const uint2*)ll;
}

// ---------------------------------------------------------------------------
// Launch
// ---------------------------------------------------------------------------
extern "C" void kernel_launch(void* const* d_in, const int* in_sizes, int n_in,
                              void* d_out, int out_size)
{
    const float* query  = (const float*)d_in[0];
    const float* value  = (const float*)d_in[1];
    const float* refp   = (const float*)d_in[2];
    const int*   shapes = (const int*)  d_in[3];
    const int*   starts = (const int*)  d_in[4];
    const float* Wv  = (const float*)d_in[5];
    const float* bv  = (const float*)d_in[6];
    const float* Wso = (const float*)d_in[7];
    const float* bso = (const float*)d_in[8];
    const float* Waw = (const float*)d_in[9];
    const float* baw = (const float*)d_in[10];
    const float* Wo  = (const float*)d_in[11];
    const float* bo  = (const float*)d_in[12];
    float* out = (float*)d_out;

    const int M = in_sizes[0] / EDIM;   // 40394

    float *pQA, *pBiasQA;
    __half* pVh;
    __nv_bfloat16 *pAval, *pAq, *pAtmp, *pBv, *pBqa, *pBo;
    cudaGetSymbolAddress((void**)&pVh,    g_Vh);
    cudaGetSymbolAddress((void**)&pQA,    g_QA);
    cudaGetSymbolAddress((void**)&pBiasQA,g_biasQA);
    cudaGetSymbolAddress((void**)&pAval,  g_Aval);
    cudaGetSymbolAddress((void**)&pAq,    g_Aq);
    cudaGetSymbolAddress((void**)&pAtmp,  g_Atmp);
    cudaGetSymbolAddress((void**)&pBv,    g_Bv);
    cudaGetSymbolAddress((void**)&pBqa,   g_Bqa);
    cudaGetSymbolAddress((void**)&pBo,    g_Bo);

    cudaFuncSetAttribute(gemm_vqa, cudaFuncAttributeMaxDynamicSharedMemorySize, SMEM_W);
    cudaFuncSetAttribute(gemm_out, cudaFuncAttributeMaxDynamicSharedMemorySize, SMEM_N);

    const int n4 = M * (EDIM / 4);
    const int cvtB = (n4 + 255) / 256;
    const int wB   = (229760 + 255) / 256;
    const int mTiles = (M + 127) / 128;   // 316

    prep_all<<<2 * cvtB + wB, 256>>>(value, query, Wv, Wso, Waw, Wo, bso, baw,
                                     n4, cvtB);
    gemm_vqa<<<dim3(mTiles, 5), 256, SMEM_W>>>(
        pAval, pBv, bv, pVh, pAq, pBqa, pBiasQA, pQA, M);
    msda_sample4<<<(M + 3) / 4, 256>>>(pVh, pQA, refp, shapes, starts, pAtmp, M);
    gemm_out<<<mTiles * 4, 256, SMEM_N>>>(pAtmp, pBo, bo, query, out, M);
}